// round 6
// baseline (speedup 1.0000x reference)
#include <cuda_runtime.h>
#include <cuda_bf16.h>
#include <math.h>
#include <stdint.h>

#define NL 16
#define NT 2048
#define ND 2048
#define NR 128
#define NK 1024   // top-k capacity (T * 0.5)

// Scratch (no device allocation allowed -> __device__ globals)
__device__ float g_probs[NL * NT];
__device__ int   g_order[NL * NT];

// Pre-split bf16 hi/lo scratch (Dekker split of fp32)
__device__ __nv_bfloat16 g_Hh[67108864];   // hidden hi  [l][t][d]
__device__ __nv_bfloat16 g_Hl[67108864];   // hidden lo
__device__ __nv_bfloat16 g_Wh[67108864];   // W_s1 hi, TRANSPOSED [l][e][d]
__device__ __nv_bfloat16 g_Wl[67108864];   // W_s1 lo

// ===========================================================================
// Helpers (sm_80-compatible PTX only)
// ===========================================================================
__device__ __forceinline__ uint32_t smem_u32(const void* p) {
    uint32_t a;
    asm("{ .reg .u64 t; cvta.to.shared.u64 t, %1; cvt.u32.u64 %0, t; }" : "=r"(a) : "l"(p));
    return a;
}
__device__ __forceinline__ void ldsm_x4(uint32_t* d, uint32_t addr) {
    asm volatile("ldmatrix.sync.aligned.m8n8.x4.shared.b16 {%0,%1,%2,%3}, [%4];"
                 : "=r"(d[0]), "=r"(d[1]), "=r"(d[2]), "=r"(d[3]) : "r"(addr));
}
__device__ __forceinline__ void mma_bf16(float* c, const uint32_t* a, uint32_t b0, uint32_t b1) {
    asm volatile(
        "mma.sync.aligned.m16n8k16.row.col.f32.bf16.bf16.f32 "
        "{%0,%1,%2,%3}, {%4,%5,%6,%7}, {%8,%9}, {%0,%1,%2,%3};"
        : "+f"(c[0]), "+f"(c[1]), "+f"(c[2]), "+f"(c[3])
        : "r"(a[0]), "r"(a[1]), "r"(a[2]), "r"(a[3]), "r"(b0), "r"(b1));
}
__device__ __forceinline__ void mma_tf32(float* c, const uint32_t* a, const uint32_t* b) {
    asm volatile(
        "mma.sync.aligned.m16n8k8.row.col.f32.tf32.tf32.f32 "
        "{%0,%1,%2,%3}, {%4,%5,%6,%7}, {%8,%9}, {%0,%1,%2,%3};"
        : "+f"(c[0]), "+f"(c[1]), "+f"(c[2]), "+f"(c[3])
        : "r"(a[0]), "r"(a[1]), "r"(a[2]), "r"(a[3]), "r"(b[0]), "r"(b[1]));
}
// bf16 Dekker split of two fp32 -> packed hi word + lo word
__device__ __forceinline__ void split2(float x, float y, uint32_t& h, uint32_t& l) {
    __nv_bfloat16 hx = __float2bfloat16_rn(x);
    __nv_bfloat16 hy = __float2bfloat16_rn(y);
    __nv_bfloat16 lx = __float2bfloat16_rn(x - __bfloat162float(hx));
    __nv_bfloat16 ly = __float2bfloat16_rn(y - __bfloat162float(hy));
    __nv_bfloat162 th = __halves2bfloat162(hx, hy);
    __nv_bfloat162 tl = __halves2bfloat162(lx, ly);
    h = *reinterpret_cast<uint32_t*>(&th);
    l = *reinterpret_cast<uint32_t*>(&tl);
}
// tf32 split: hi = rna(x), lo = rna(x - hi)  (covers ~24 mantissa bits)
__device__ __forceinline__ void tsplit(float x, uint32_t& h, uint32_t& l) {
    asm("cvt.rna.tf32.f32 %0, %1;" : "=r"(h) : "f"(x));
    float hf = __uint_as_float(h);
    asm("cvt.rna.tf32.f32 %0, %1;" : "=r"(l) : "f"(x - hf));
}
#define CP16(d, s) asm volatile("cp.async.cg.shared.global [%0], [%1], 16;\n" :: "r"(d), "l"(s))
#define CPCOMMIT() asm volatile("cp.async.commit_group;\n" ::: "memory")
#define CPWAIT1()  asm volatile("cp.async.wait_group 1;\n" ::: "memory")
#define CPWAIT0()  asm volatile("cp.async.wait_group 0;\n" ::: "memory")

// ---------------------------------------------------------------------------
// Pre-split kernels
// ---------------------------------------------------------------------------
__global__ __launch_bounds__(256) void split_h_kernel(const float* __restrict__ h)
{
    size_t idx = ((size_t)blockIdx.x * 256 + threadIdx.x) * 4;
    float4 v = *(const float4*)(h + idx);
    uint32_t h0, l0, h1, l1;
    split2(v.x, v.y, h0, l0);
    split2(v.z, v.w, h1, l1);
    *(uint2*)&g_Hh[idx] = make_uint2(h0, h1);
    *(uint2*)&g_Hl[idx] = make_uint2(l0, l1);
}

// W_s1 [l][d][e] -> g_W{h,l} transposed [l][e][d]
__global__ __launch_bounds__(256) void split_w_kernel(const float* __restrict__ W)
{
    __shared__ float s[64][129];
    const int l = blockIdx.z, kb = blockIdx.y, eb = blockIdx.x;
    const int tid = threadIdx.x;
    const float* src = W + ((size_t)l * ND + kb * 64) * ND + eb * 128;
    #pragma unroll
    for (int i = 0; i < 8; i++) {
        int idx = tid + i * 256;          // 2048 float4 = 64k x 128e
        int k = idx >> 5;
        int e4 = (idx & 31) * 4;
        float4 v = *(const float4*)(src + (size_t)k * ND + e4);
        s[k][e4] = v.x; s[k][e4 + 1] = v.y; s[k][e4 + 2] = v.z; s[k][e4 + 3] = v.w;
    }
    __syncthreads();
    const int e  = tid >> 1;
    const int kh = (tid & 1) * 32;
    uint32_t hw[16], lw[16];
    #pragma unroll
    for (int j = 0; j < 16; j++)
        split2(s[kh + 2 * j][e], s[kh + 2 * j + 1][e], hw[j], lw[j]);
    size_t doff = ((size_t)l * ND + eb * 128 + e) * ND + kb * 64 + kh;
    #pragma unroll
    for (int q = 0; q < 4; q++) {
        *(uint4*)&g_Wh[doff + q * 8] = make_uint4(hw[4*q], hw[4*q+1], hw[4*q+2], hw[4*q+3]);
        *(uint4*)&g_Wl[doff + q * 8] = make_uint4(lw[4*q], lw[4*q+1], lw[4*q+2], lw[4*q+3]);
    }
}

// ---------------------------------------------------------------------------
// Router on tensor cores: tf32 hi/lo x 4 products (~fp32 accuracy).
// CTA: 128 tokens x 128 R, K chunks of 32, double-buffered smem.
// smem (tf32 u32, row stride 36 words): AH,AL[128][36], BH,BL[128][36] /buffer
// 8 warps 2(m) x 4(n) -> warp tile 64 x 32.
// ---------------------------------------------------------------------------
#define RSTR    36
#define R_AL    18432
#define R_BH    36864
#define R_BL    55296
#define R_BUF   73728
#define R_MISC  147456
#define R_SM    148480

__global__ __launch_bounds__(256) void router_tc(
    const float* __restrict__ hidden,
    const float* __restrict__ W_r1,
    const float* __restrict__ b_r1,
    const float* __restrict__ W_r2,
    const float* __restrict__ b_r2)
{
    extern __shared__ char sm[];
    const int l   = blockIdx.y;
    const int t0  = blockIdx.x * 128;
    const int tid = threadIdx.x;
    const int w   = tid >> 5;
    const int lane = tid & 31;

    float* sB1 = (float*)(sm + R_MISC);
    float* sW2 = (float*)(sm + R_MISC + 512);
    if (tid < NR) {
        sB1[tid] = b_r1[l * NR + tid];
        sW2[tid] = W_r2[l * NR + tid];
    }

    const int r  = tid >> 1;
    const int kh = (tid & 1) * 16;
    const float* aP = hidden + ((size_t)(l * NT + t0 + r)) * ND + kh;
    const float* bP = W_r1 + (size_t)l * ND * NR + r;
    const uint32_t stsOff = (uint32_t)(r * RSTR + kh) * 4;

    const int wm = w & 1, wn = w >> 1;
    const int m_base = wm * 64, n_base = wn * 32;

    float acc[4][4][4];
    #pragma unroll
    for (int i = 0; i < 4; i++)
        #pragma unroll
        for (int g = 0; g < 4; g++)
            #pragma unroll
            for (int e = 0; e < 4; e++) acc[i][g][e] = 0.f;

    float4 av[4];
    float  bv[16];

    #define R_LOAD(c) do {                                                      \
        const int kk0 = (c) * 32;                                               \
        _Pragma("unroll")                                                       \
        for (int j = 0; j < 4; j++) av[j] = *(const float4*)(aP + kk0 + j * 4); \
        _Pragma("unroll")                                                       \
        for (int i = 0; i < 16; i++) bv[i] = __ldg(bP + (size_t)(kk0 + kh + i) * NR); \
    } while (0)

    #define R_STORE(buf) do {                                                   \
        char* base = sm + (buf) * R_BUF;                                        \
        uint32_t th[16], tl[16];                                                \
        const float* af = (const float*)av;                                     \
        _Pragma("unroll")                                                       \
        for (int i = 0; i < 16; i++) tsplit(af[i], th[i], tl[i]);               \
        _Pragma("unroll")                                                       \
        for (int q = 0; q < 4; q++) {                                           \
            *(uint4*)(base + stsOff + q * 16)        = make_uint4(th[4*q], th[4*q+1], th[4*q+2], th[4*q+3]); \
            *(uint4*)(base + R_AL + stsOff + q * 16) = make_uint4(tl[4*q], tl[4*q+1], tl[4*q+2], tl[4*q+3]); \
        }                                                                       \
        _Pragma("unroll")                                                       \
        for (int i = 0; i < 16; i++) tsplit(bv[i], th[i], tl[i]);               \
        _Pragma("unroll")                                                       \
        for (int q = 0; q < 4; q++) {                                           \
            *(uint4*)(base + R_BH + stsOff + q * 16) = make_uint4(th[4*q], th[4*q+1], th[4*q+2], th[4*q+3]); \
            *(uint4*)(base + R_BL + stsOff + q * 16) = make_uint4(tl[4*q], tl[4*q+1], tl[4*q+2], tl[4*q+3]); \
        }                                                                       \
    } while (0)

    #define R_COMPUTE(buf) do {                                                 \
        const char* bb = sm + (buf) * R_BUF;                                    \
        const uint32_t* AHp = (const uint32_t*)bb;                              \
        const uint32_t* ALp = (const uint32_t*)(bb + R_AL);                     \
        const uint32_t* BHp = (const uint32_t*)(bb + R_BH);                     \
        const uint32_t* BLp = (const uint32_t*)(bb + R_BL);                     \
        _Pragma("unroll")                                                       \
        for (int ks = 0; ks < 4; ks++) {                                        \
            const int k0 = ks * 8;                                              \
            const int ar = lane >> 2, ac = k0 + (lane & 3);                     \
            uint32_t Ah[4][4], Al[4][4], Bh[4][2], Bl[4][2];                    \
            _Pragma("unroll")                                                   \
            for (int i = 0; i < 4; i++) {                                       \
                int b0 = (m_base + i * 16 + ar) * RSTR + ac;                    \
                Ah[i][0] = AHp[b0];            Ah[i][1] = AHp[b0 + 8 * RSTR];   \
                Ah[i][2] = AHp[b0 + 4];        Ah[i][3] = AHp[b0 + 8 * RSTR + 4]; \
                Al[i][0] = ALp[b0];            Al[i][1] = ALp[b0 + 8 * RSTR];   \
                Al[i][2] = ALp[b0 + 4];        Al[i][3] = ALp[b0 + 8 * RSTR + 4]; \
            }                                                                   \
            _Pragma("unroll")                                                   \
            for (int g = 0; g < 4; g++) {                                       \
                int nb = (n_base + g * 8 + (lane >> 2)) * RSTR + k0 + (lane & 3); \
                Bh[g][0] = BHp[nb]; Bh[g][1] = BHp[nb + 4];                     \
                Bl[g][0] = BLp[nb]; Bl[g][1] = BLp[nb + 4];                     \
            }                                                                   \
            _Pragma("unroll")                                                   \
            for (int i = 0; i < 4; i++)                                         \
                _Pragma("unroll")                                               \
                for (int g = 0; g < 4; g++) {                                   \
                    mma_tf32(acc[i][g], Ah[i], Bh[g]);                          \
                    mma_tf32(acc[i][g], Ah[i], Bl[g]);                          \
                    mma_tf32(acc[i][g], Al[i], Bh[g]);                          \
                    mma_tf32(acc[i][g], Al[i], Bl[g]);                          \
                }                                                               \
        }                                                                       \
    } while (0)

    R_LOAD(0);
    R_STORE(0);
    __syncthreads();

    for (int c = 0; c < ND / 32; c++) {
        if (c < ND / 32 - 1) R_LOAD(c + 1);
        R_COMPUTE(c & 1);
        if (c < ND / 32 - 1) R_STORE((c + 1) & 1);   // writes other buffer: safe
        __syncthreads();
    }

    // epilogue: h = relu(acc + b_r1) -> smem, then dot with W_r2 + sigmoid
    float* sprob = (float*)sm;   // reuse buffer 0, stride 132 floats
    #pragma unroll
    for (int i = 0; i < 4; i++) {
        #pragma unroll
        for (int g = 0; g < 4; g++) {
            int row0 = m_base + i * 16 + (lane >> 2);
            int col  = n_base + g * 8 + (lane & 3) * 2;
            sprob[row0 * 132 + col]         = fmaxf(acc[i][g][0] + sB1[col], 0.f);
            sprob[row0 * 132 + col + 1]     = fmaxf(acc[i][g][1] + sB1[col + 1], 0.f);
            sprob[(row0 + 8) * 132 + col]   = fmaxf(acc[i][g][2] + sB1[col], 0.f);
            sprob[(row0 + 8) * 132 + col+1] = fmaxf(acc[i][g][3] + sB1[col + 1], 0.f);
        }
    }
    __syncthreads();

    const int tok  = tid >> 1;
    const int half = (tid & 1) * 64;
    float s = 0.f;
    #pragma unroll
    for (int j = 0; j < 64; j++)
        s += sprob[tok * 132 + half + j] * sW2[half + j];
    s += __shfl_xor_sync(0xffffffffu, s, 1);
    if (!(tid & 1)) {
        float logit = s + b_r2[l];
        g_probs[l * NT + t0 + tok] = 1.0f / (1.0f + expf(-logit));
    }
}

// ---------------------------------------------------------------------------
// Top-K via exhaustive rank (proven)
// ---------------------------------------------------------------------------
__global__ __launch_bounds__(1024) void topk_kernel()
{
    __shared__ float sp[NT];
    const int l = blockIdx.x;
    for (int i = threadIdx.x; i < NT; i += 1024) sp[i] = g_probs[l * NT + i];
    __syncthreads();

    #pragma unroll
    for (int ii = 0; ii < 2; ii++) {
        int t = threadIdx.x + ii * 1024;
        float p = sp[t];
        int rank = 0;
        #pragma unroll 4
        for (int j = 0; j < NT; j++) {
            float q = sp[j];
            rank += (q > p) || (q == p && j < t);
        }
        g_order[l * NT + rank] = t;
    }
}

// ---------------------------------------------------------------------------
// Copy s2 rows (proven)
// ---------------------------------------------------------------------------
__global__ __launch_bounds__(128) void copy_kernel(
    const float* __restrict__ s2, float* __restrict__ out)
{
    const int l = blockIdx.x >> 10;
    const int i = blockIdx.x & (NK - 1);
    const int t = g_order[l * NT + i];
    const float4* src = (const float4*)(s2 + ((size_t)l * NT + t) * ND);
    float4*       dst = (float4*)(out + ((size_t)l * NT + t) * ND);
    #pragma unroll
    for (int j = threadIdx.x; j < ND / 4; j += 128) dst[j] = src[j];
}

// ---------------------------------------------------------------------------
// s1 GEMM: HMMA bf16 hi/lo (3 products), cp.async from pre-split scratch.
// CTA 128(M, gathered) x 128(N), K-chunk 32, double-buffered smem.
// smem bf16 stride 40; Ah/Al/Bh/Bl 10240 B each per buffer.
// ---------------------------------------------------------------------------
#define KC       32
#define ASTRIDE  40
#define OFF_AL   10240
#define OFF_BH   20480
#define OFF_BL   30720
#define BUFB     40960
#define SM_ROWS  81920
#define SM_TOTAL 82432

__global__ __launch_bounds__(256, 2) void s1_gemm_cp(
    const float* __restrict__ b_s1,
    float* __restrict__ out)
{
    extern __shared__ char sm[];
    const int l   = blockIdx.z;
    const int n0  = blockIdx.x * 128;
    const int r0  = blockIdx.y * 128;
    const int tid = threadIdx.x;
    const int w   = tid >> 5;
    const int lane = tid & 31;
    const uint32_t sbase = smem_u32(sm);

    int* srows = (int*)(sm + SM_ROWS);
    if (tid < 128) srows[tid] = g_order[l * NT + NK + r0 + tid];
    __syncthreads();

    const int row = tid >> 1;
    const int kh  = (tid & 1) * 16;
    const __nv_bfloat16* aH = g_Hh + ((size_t)l * NT + srows[row]) * ND + kh;
    const __nv_bfloat16* aL = g_Hl + ((size_t)l * NT + srows[row]) * ND + kh;
    const __nv_bfloat16* bH = g_Wh + ((size_t)l * ND + n0 + row) * ND + kh;
    const __nv_bfloat16* bL = g_Wl + ((size_t)l * ND + n0 + row) * ND + kh;
    const uint32_t stsA = (uint32_t)(row * ASTRIDE + kh) * 2;

    const int wm = w & 1, wn = w >> 1;
    const int m_base = wm * 64, n_base = wn * 32;

    float acc[4][4][4];
    #pragma unroll
    for (int i = 0; i < 4; i++)
        #pragma unroll
        for (int g = 0; g < 4; g++)
            #pragma unroll
            for (int e = 0; e < 4; e++) acc[i][g][e] = 0.f;

    #define ISSUE(cc, buf) do {                                                 \
        uint32_t bb = sbase + (buf) * BUFB;                                     \
        const __nv_bfloat16* pah = aH + (cc) * KC;                              \
        const __nv_bfloat16* pal = aL + (cc) * KC;                              \
        const __nv_bfloat16* pbh = bH + (cc) * KC;                              \
        const __nv_bfloat16* pbl = bL + (cc) * KC;                              \
        CP16(bb + stsA,               pah); CP16(bb + stsA + 16,               pah + 8); \
        CP16(bb + OFF_AL + stsA,      pal); CP16(bb + OFF_AL + stsA + 16,      pal + 8); \
        CP16(bb + OFF_BH + stsA,      pbh); CP16(bb + OFF_BH + stsA + 16,      pbh + 8); \
        CP16(bb + OFF_BL + stsA,      pbl); CP16(bb + OFF_BL + stsA + 16,      pbl + 8); \
        CPCOMMIT();                                                             \
    } while (0)

    const int frow = lane & 15;
    const int fcol = (lane >> 4) * 8;

    #define COMPUTE_CHUNK(buf) do {                                             \
        const uint32_t bb = sbase + (buf) * BUFB;                               \
        _Pragma("unroll")                                                       \
        for (int s = 0; s < 2; s++) {                                           \
            const int k0 = s * 16;                                              \
            uint32_t ah[4][4], al[4][4], bh[2][4], bl[2][4];                    \
            const uint32_t a_ad = bb + ((m_base + frow) * ASTRIDE + k0 + fcol) * 2; \
            _Pragma("unroll")                                                   \
            for (int i = 0; i < 4; i++) {                                       \
                ldsm_x4(ah[i], a_ad + i * (16 * ASTRIDE * 2));                  \
                ldsm_x4(al[i], a_ad + OFF_AL + i * (16 * ASTRIDE * 2));         \
            }                                                                   \
            const uint32_t b_ad = bb + OFF_BH + ((n_base + frow) * ASTRIDE + k0 + fcol) * 2; \
            _Pragma("unroll")                                                   \
            for (int j = 0; j < 2; j++) {                                       \
                ldsm_x4(bh[j], b_ad + j * (16 * ASTRIDE * 2));                  \
                ldsm_x4(bl[j], b_ad + (OFF_BL - OFF_BH) + j * (16 * ASTRIDE * 2)); \
            }                                                                   \
            _Pragma("unroll")                                                   \
            for (int i = 0; i < 4; i++) {                                       \
                _Pragma("unroll")                                               \
                for (int jj = 0; jj < 2; jj++) {                                \
                    _Pragma("unroll")                                           \
                    for (int hi = 0; hi < 2; hi++) {                            \
                        const int g = jj * 2 + hi;                              \
                        mma_bf16(acc[i][g], ah[i], bh[jj][hi], bh[jj][hi + 2]); \
                        mma_bf16(acc[i][g], ah[i], bl[jj][hi], bl[jj][hi + 2]); \
                        mma_bf16(acc[i][g], al[i], bh[jj][hi], bh[jj][hi + 2]); \
                    }                                                           \
                }                                                               \
            }                                                                   \
        }                                                                       \
    } while (0)

    ISSUE(0, 0);
    ISSUE(1, 1);

    for (int c = 0; c < ND / KC; c++) {
        if (c < ND / KC - 1) CPWAIT1(); else CPWAIT0();
        __syncthreads();
        COMPUTE_CHUNK(c & 1);
        __syncthreads();
        if (c < ND / KC - 2) ISSUE(c + 2, c & 1);
    }

    // Epilogue
    const int tq = lane >> 2;
    const int tr = lane & 3;
    #pragma unroll
    for (int g = 0; g < 4; g++) {
        const int col = n_base + g * 8 + tr * 2;
        const float bx = __ldg(b_s1 + l * ND + n0 + col);
        const float by = __ldg(b_s1 + l * ND + n0 + col + 1);
        #pragma unroll
        for (int i = 0; i < 4; i++) {
            const int rl = m_base + i * 16 + tq;
            float* o0 = out + ((size_t)l * NT + srows[rl])     * ND + n0 + col;
            float* o1 = out + ((size_t)l * NT + srows[rl + 8]) * ND + n0 + col;
            *(float2*)o0 = make_float2(acc[i][g][0] + bx, acc[i][g][1] + by);
            *(float2*)o1 = make_float2(acc[i][g][2] + bx, acc[i][g][3] + by);
        }
    }
}

// ---------------------------------------------------------------------------
extern "C" void kernel_launch(void* const* d_in, const int* in_sizes, int n_in,
                              void* d_out, int out_size)
{
    const float* hidden = (const float*)d_in[0];
    const float* s2     = (const float*)d_in[1];
    const float* W_r1   = (const float*)d_in[2];
    const float* b_r1   = (const float*)d_in[3];
    const float* W_r2   = (const float*)d_in[4];
    const float* b_r2   = (const float*)d_in[5];
    const float* W_s1   = (const float*)d_in[6];
    const float* b_s1   = (const float*)d_in[7];
    float* out = (float*)d_out;

    static bool attr_done = false;
    if (!attr_done) {
        cudaFuncSetAttribute(s1_gemm_cp, cudaFuncAttributeMaxDynamicSharedMemorySize, SM_TOTAL);
        cudaFuncSetAttribute(router_tc, cudaFuncAttributeMaxDynamicSharedMemorySize, R_SM);
        attr_done = true;
    }

    split_h_kernel<<<65536, 256>>>(hidden);
    split_w_kernel<<<dim3(16, 32, 16), 256>>>(W_s1);
    router_tc<<<dim3(16, 16), 256, R_SM>>>(hidden, W_r1, b_r1, W_r2, b_r2);
    topk_kernel<<<NL, 1024>>>();
    copy_kernel<<<NL * NK, 128>>>(s2, out);
    dim3 g(ND / 128, (NT - NK) / 128, NL);
    s1_gemm_cp<<<g, 256, SM_TOTAL>>>(b_s1, out);
}

// round 7
// speedup vs baseline: 1.0374x; 1.0374x over previous
#include <cuda_runtime.h>
#include <cuda_bf16.h>
#include <math.h>
#include <stdint.h>

#define NL 16
#define NT 2048
#define ND 2048
#define NR 128
#define NK 1024   // top-k capacity (T * 0.5)

// Scratch (no device allocation allowed -> __device__ globals)
__device__ float g_probs[NL * NT];
__device__ int   g_order[NL * NT];

// Pre-split bf16 hi/lo scratch (Dekker split of fp32)
__device__ __nv_bfloat16 g_Hh[67108864];   // hidden hi  [l][t][d]
__device__ __nv_bfloat16 g_Hl[67108864];   // hidden lo
__device__ __nv_bfloat16 g_Wh[67108864];   // W_s1 hi, TRANSPOSED [l][e][d]
__device__ __nv_bfloat16 g_Wl[67108864];   // W_s1 lo

// ===========================================================================
// Helpers (sm_80-compatible PTX only)
// ===========================================================================
__device__ __forceinline__ uint32_t smem_u32(const void* p) {
    uint32_t a;
    asm("{ .reg .u64 t; cvta.to.shared.u64 t, %1; cvt.u32.u64 %0, t; }" : "=r"(a) : "l"(p));
    return a;
}
__device__ __forceinline__ void ldsm_x4(uint32_t* d, uint32_t addr) {
    asm volatile("ldmatrix.sync.aligned.m8n8.x4.shared.b16 {%0,%1,%2,%3}, [%4];"
                 : "=r"(d[0]), "=r"(d[1]), "=r"(d[2]), "=r"(d[3]) : "r"(addr));
}
__device__ __forceinline__ void mma_bf16(float* c, const uint32_t* a, uint32_t b0, uint32_t b1) {
    asm volatile(
        "mma.sync.aligned.m16n8k16.row.col.f32.bf16.bf16.f32 "
        "{%0,%1,%2,%3}, {%4,%5,%6,%7}, {%8,%9}, {%0,%1,%2,%3};"
        : "+f"(c[0]), "+f"(c[1]), "+f"(c[2]), "+f"(c[3])
        : "r"(a[0]), "r"(a[1]), "r"(a[2]), "r"(a[3]), "r"(b0), "r"(b1));
}
// bf16 Dekker split of two fp32 -> packed hi word + lo word
__device__ __forceinline__ void split2(float x, float y, uint32_t& h, uint32_t& l) {
    __nv_bfloat16 hx = __float2bfloat16_rn(x);
    __nv_bfloat16 hy = __float2bfloat16_rn(y);
    __nv_bfloat16 lx = __float2bfloat16_rn(x - __bfloat162float(hx));
    __nv_bfloat16 ly = __float2bfloat16_rn(y - __bfloat162float(hy));
    __nv_bfloat162 th = __halves2bfloat162(hx, hy);
    __nv_bfloat162 tl = __halves2bfloat162(lx, ly);
    h = *reinterpret_cast<uint32_t*>(&th);
    l = *reinterpret_cast<uint32_t*>(&tl);
}
#define CP16(d, s) asm volatile("cp.async.cg.shared.global [%0], [%1], 16;\n" :: "r"(d), "l"(s))
#define CPCOMMIT() asm volatile("cp.async.commit_group;\n" ::: "memory")
#define CPWAIT2()  asm volatile("cp.async.wait_group 2;\n" ::: "memory")

// ---------------------------------------------------------------------------
// Pre-split kernels
// ---------------------------------------------------------------------------
__global__ __launch_bounds__(256) void split_h_kernel(const float* __restrict__ h)
{
    size_t idx = ((size_t)blockIdx.x * 256 + threadIdx.x) * 4;
    float4 v = *(const float4*)(h + idx);
    uint32_t h0, l0, h1, l1;
    split2(v.x, v.y, h0, l0);
    split2(v.z, v.w, h1, l1);
    *(uint2*)&g_Hh[idx] = make_uint2(h0, h1);
    *(uint2*)&g_Hl[idx] = make_uint2(l0, l1);
}

// W_s1 [l][d][e] -> g_W{h,l} transposed [l][e][d]
__global__ __launch_bounds__(256) void split_w_kernel(const float* __restrict__ W)
{
    __shared__ float s[64][129];
    const int l = blockIdx.z, kb = blockIdx.y, eb = blockIdx.x;
    const int tid = threadIdx.x;
    const float* src = W + ((size_t)l * ND + kb * 64) * ND + eb * 128;
    #pragma unroll
    for (int i = 0; i < 8; i++) {
        int idx = tid + i * 256;          // 2048 float4 = 64k x 128e
        int k = idx >> 5;
        int e4 = (idx & 31) * 4;
        float4 v = *(const float4*)(src + (size_t)k * ND + e4);
        s[k][e4] = v.x; s[k][e4 + 1] = v.y; s[k][e4 + 2] = v.z; s[k][e4 + 3] = v.w;
    }
    __syncthreads();
    const int e  = tid >> 1;
    const int kh = (tid & 1) * 32;
    uint32_t hw[16], lw[16];
    #pragma unroll
    for (int j = 0; j < 16; j++)
        split2(s[kh + 2 * j][e], s[kh + 2 * j + 1][e], hw[j], lw[j]);
    size_t doff = ((size_t)l * ND + eb * 128 + e) * ND + kb * 64 + kh;
    #pragma unroll
    for (int q = 0; q < 4; q++) {
        *(uint4*)&g_Wh[doff + q * 8] = make_uint4(hw[4*q], hw[4*q+1], hw[4*q+2], hw[4*q+3]);
        *(uint4*)&g_Wl[doff + q * 8] = make_uint4(lw[4*q], lw[4*q+1], lw[4*q+2], lw[4*q+3]);
    }
}

// ---------------------------------------------------------------------------
// Router (proven R1 fp32 version)
// ---------------------------------------------------------------------------
__global__ __launch_bounds__(256) void router_kernel(
    const float* __restrict__ hidden,
    const float* __restrict__ W_r1,
    const float* __restrict__ b_r1,
    const float* __restrict__ W_r2,
    const float* __restrict__ b_r2)
{
    __shared__ float sW[32][NR];
    __shared__ float sH[64][33];
    __shared__ float sB1[NR];
    __shared__ float sW2[NR];

    const int l  = blockIdx.x >> 5;
    const int t0 = (blockIdx.x & 31) * 64;
    const int tid = threadIdx.x;

    if (tid < NR) {
        sB1[tid] = b_r1[l * NR + tid];
        sW2[tid] = W_r2[l * NR + tid];
    }

    const int tok   = tid >> 2;
    const int lane4 = tid & 3;

    float acc[32];
    #pragma unroll
    for (int i = 0; i < 32; i++) acc[i] = 0.f;

    const float* hbase = hidden + ((size_t)l * NT + t0) * ND;
    const float* wbase = W_r1 + (size_t)l * ND * NR;

    for (int d0 = 0; d0 < ND; d0 += 32) {
        #pragma unroll
        for (int j = 0; j < 2; j++) {
            int e   = tid + j * 256;
            int row = e >> 3;
            int c4  = (e & 7) * 4;
            float4 v = *(const float4*)(hbase + (size_t)row * ND + d0 + c4);
            sH[row][c4 + 0] = v.x; sH[row][c4 + 1] = v.y;
            sH[row][c4 + 2] = v.z; sH[row][c4 + 3] = v.w;
        }
        #pragma unroll
        for (int j = 0; j < 4; j++) {
            int e  = tid + j * 256;
            int dd = e >> 5;
            int c4 = (e & 31) * 4;
            float4 v = *(const float4*)(wbase + (size_t)(d0 + dd) * NR + c4);
            *(float4*)&sW[dd][c4] = v;
        }
        __syncthreads();

        #pragma unroll
        for (int dd = 0; dd < 32; dd++) {
            float x = sH[tok][dd];
            #pragma unroll
            for (int j = 0; j < 8; j++) {
                float4 w = *(const float4*)&sW[dd][lane4 * 4 + j * 16];
                acc[j * 4 + 0] += x * w.x;
                acc[j * 4 + 1] += x * w.y;
                acc[j * 4 + 2] += x * w.z;
                acc[j * 4 + 3] += x * w.w;
            }
        }
        __syncthreads();
    }

    float part = 0.f;
    #pragma unroll
    for (int j = 0; j < 8; j++) {
        #pragma unroll
        for (int k = 0; k < 4; k++) {
            int r = lane4 * 4 + j * 16 + k;
            float h = acc[j * 4 + k] + sB1[r];
            h = fmaxf(h, 0.f);
            part += h * sW2[r];
        }
    }
    part += __shfl_down_sync(0xffffffffu, part, 2, 4);
    part += __shfl_down_sync(0xffffffffu, part, 1, 4);
    if (lane4 == 0) {
        float logit = part + b_r2[l];
        g_probs[l * NT + t0 + tok] = 1.0f / (1.0f + expf(-logit));
    }
}

// ---------------------------------------------------------------------------
// Top-K via exhaustive rank — parallelized: 8 blocks/layer, 1 token/thread.
// ---------------------------------------------------------------------------
__global__ __launch_bounds__(256) void topk_kernel()
{
    __shared__ float sp[NT];
    const int l   = blockIdx.x >> 3;
    const int seg = blockIdx.x & 7;
    for (int i = threadIdx.x; i < NT; i += 256) sp[i] = g_probs[l * NT + i];
    __syncthreads();

    const int t = seg * 256 + threadIdx.x;
    const float p = sp[t];
    int rank = 0;
    #pragma unroll 8
    for (int j = 0; j < NT; j++) {
        float q = sp[j];
        rank += (q > p) || (q == p && j < t);
    }
    g_order[l * NT + rank] = t;
}

// ---------------------------------------------------------------------------
// Copy s2 rows (proven)
// ---------------------------------------------------------------------------
__global__ __launch_bounds__(128) void copy_kernel(
    const float* __restrict__ s2, float* __restrict__ out)
{
    const int l = blockIdx.x >> 10;
    const int i = blockIdx.x & (NK - 1);
    const int t = g_order[l * NT + i];
    const float4* src = (const float4*)(s2 + ((size_t)l * NT + t) * ND);
    float4*       dst = (float4*)(out + ((size_t)l * NT + t) * ND);
    #pragma unroll
    for (int j = threadIdx.x; j < ND / 4; j += 128) dst[j] = src[j];
}

// ---------------------------------------------------------------------------
// s1 GEMM: HMMA bf16 hi/lo (3 products), all operands via cp.async from
// pre-split scratch. CTA 128(M, gathered) x 128(N), K-chunk 32.
// 4-deep pipeline, ONE __syncthreads per chunk, no in-loop conversion.
// Per buffer (bf16, row stride 40): Ah/Al/Bh/Bl 10240 B each = 40960 B.
// 4 buffers = 163840 B + rows = fits in 228 KB (1 CTA/SM).
// ---------------------------------------------------------------------------
#define KC       32
#define ASTRIDE  40
#define OFF_AL   10240
#define OFF_BH   20480
#define OFF_BL   30720
#define BUFB     40960
#define SM_ROWS  163840
#define SM_TOTAL 164352

__global__ __launch_bounds__(256, 1) void s1_gemm_cp(
    const float* __restrict__ b_s1,
    float* __restrict__ out)
{
    extern __shared__ char sm[];
    const int l   = blockIdx.z;
    const int n0  = blockIdx.x * 128;
    const int r0  = blockIdx.y * 128;
    const int tid = threadIdx.x;
    const int w   = tid >> 5;
    const int lane = tid & 31;
    const uint32_t sbase = smem_u32(sm);

    int* srows = (int*)(sm + SM_ROWS);
    if (tid < 128) srows[tid] = g_order[l * NT + NK + r0 + tid];
    __syncthreads();

    const int row = tid >> 1;
    const int kh  = (tid & 1) * 16;
    const __nv_bfloat16* aH = g_Hh + ((size_t)l * NT + srows[row]) * ND + kh;
    const __nv_bfloat16* aL = g_Hl + ((size_t)l * NT + srows[row]) * ND + kh;
    const __nv_bfloat16* bH = g_Wh + ((size_t)l * ND + n0 + row) * ND + kh;
    const __nv_bfloat16* bL = g_Wl + ((size_t)l * ND + n0 + row) * ND + kh;
    const uint32_t stsA = (uint32_t)(row * ASTRIDE + kh) * 2;

    const int wm = w & 1, wn = w >> 1;
    const int m_base = wm * 64, n_base = wn * 32;

    float acc[4][4][4];
    #pragma unroll
    for (int i = 0; i < 4; i++)
        #pragma unroll
        for (int g = 0; g < 4; g++)
            #pragma unroll
            for (int e = 0; e < 4; e++) acc[i][g][e] = 0.f;

    #define ISSUE(cc, buf) do {                                                 \
        uint32_t bb = sbase + (buf) * BUFB;                                     \
        const __nv_bfloat16* pah = aH + (cc) * KC;                              \
        const __nv_bfloat16* pal = aL + (cc) * KC;                              \
        const __nv_bfloat16* pbh = bH + (cc) * KC;                              \
        const __nv_bfloat16* pbl = bL + (cc) * KC;                              \
        CP16(bb + stsA,          pah); CP16(bb + stsA + 16,          pah + 8);  \
        CP16(bb + OFF_AL + stsA, pal); CP16(bb + OFF_AL + stsA + 16, pal + 8);  \
        CP16(bb + OFF_BH + stsA, pbh); CP16(bb + OFF_BH + stsA + 16, pbh + 8);  \
        CP16(bb + OFF_BL + stsA, pbl); CP16(bb + OFF_BL + stsA + 16, pbl + 8);  \
        CPCOMMIT();                                                             \
    } while (0)

    const int frow = lane & 15;
    const int fcol = (lane >> 4) * 8;

    #define COMPUTE_CHUNK(buf) do {                                             \
        const uint32_t bb = sbase + (buf) * BUFB;                               \
        _Pragma("unroll")                                                       \
        for (int s = 0; s < 2; s++) {                                           \
            const int k0 = s * 16;                                              \
            uint32_t ah[4][4], al[4][4], bh[2][4], bl[2][4];                    \
            const uint32_t a_ad = bb + ((m_base + frow) * ASTRIDE + k0 + fcol) * 2; \
            _Pragma("unroll")                                                   \
            for (int i = 0; i < 4; i++) {                                       \
                ldsm_x4(ah[i], a_ad + i * (16 * ASTRIDE * 2));                  \
                ldsm_x4(al[i], a_ad + OFF_AL + i * (16 * ASTRIDE * 2));         \
            }                                                                   \
            const uint32_t b_ad = bb + OFF_BH + ((n_base + frow) * ASTRIDE + k0 + fcol) * 2; \
            _Pragma("unroll")                                                   \
            for (int j = 0; j < 2; j++) {                                       \
                ldsm_x4(bh[j], b_ad + j * (16 * ASTRIDE * 2));                  \
                ldsm_x4(bl[j], b_ad + (OFF_BL - OFF_BH) + j * (16 * ASTRIDE * 2)); \
            }                                                                   \
            _Pragma("unroll")                                                   \
            for (int i = 0; i < 4; i++) {                                       \
                _Pragma("unroll")                                               \
                for (int jj = 0; jj < 2; jj++) {                                \
                    _Pragma("unroll")                                           \
                    for (int hi = 0; hi < 2; hi++) {                            \
                        const int g = jj * 2 + hi;                              \
                        mma_bf16(acc[i][g], ah[i], bh[jj][hi], bh[jj][hi + 2]); \
                        mma_bf16(acc[i][g], ah[i], bl[jj][hi], bl[jj][hi + 2]); \
                        mma_bf16(acc[i][g], al[i], bh[jj][hi], bh[jj][hi + 2]); \
                    }                                                           \
                }                                                               \
            }                                                                   \
        }                                                                       \
    } while (0)

    ISSUE(0, 0);
    ISSUE(1, 1);
    ISSUE(2, 2);

    for (int c = 0; c < ND / KC; c++) {
        CPWAIT2();            // group c complete (<=2 younger pending)
        __syncthreads();      // cp.async data visible to all warps
        COMPUTE_CHUNK(c & 3);
        if (c + 3 < ND / KC) ISSUE(c + 3, (c + 3) & 3);
        // no second barrier needed: ISSUE(c+3) writes buf (c+3)&3, whose last
        // readers (COMPUTE c-1) finished before this iteration's barrier.
    }

    // Epilogue: c-frag (m16n8): c0,c1 @ (row=t/4, col=2(t%4)); c2,c3 @ row+8
    const int tq = lane >> 2;
    const int tr = lane & 3;
    #pragma unroll
    for (int g = 0; g < 4; g++) {
        const int col = n_base + g * 8 + tr * 2;
        const float bx = __ldg(b_s1 + l * ND + n0 + col);
        const float by = __ldg(b_s1 + l * ND + n0 + col + 1);
        #pragma unroll
        for (int i = 0; i < 4; i++) {
            const int rl = m_base + i * 16 + tq;
            float* o0 = out + ((size_t)l * NT + srows[rl])     * ND + n0 + col;
            float* o1 = out + ((size_t)l * NT + srows[rl + 8]) * ND + n0 + col;
            *(float2*)o0 = make_float2(acc[i][g][0] + bx, acc[i][g][1] + by);
            *(float2*)o1 = make_float2(acc[i][g][2] + bx, acc[i][g][3] + by);
        }
    }
}

// ---------------------------------------------------------------------------
extern "C" void kernel_launch(void* const* d_in, const int* in_sizes, int n_in,
                              void* d_out, int out_size)
{
    const float* hidden = (const float*)d_in[0];
    const float* s2     = (const float*)d_in[1];
    const float* W_r1   = (const float*)d_in[2];
    const float* b_r1   = (const float*)d_in[3];
    const float* W_r2   = (const float*)d_in[4];
    const float* b_r2   = (const float*)d_in[5];
    const float* W_s1   = (const float*)d_in[6];
    const float* b_s1   = (const float*)d_in[7];
    float* out = (float*)d_out;

    static bool attr_done = false;
    if (!attr_done) {
        cudaFuncSetAttribute(s1_gemm_cp, cudaFuncAttributeMaxDynamicSharedMemorySize, SM_TOTAL);
        attr_done = true;
    }

    split_h_kernel<<<65536, 256>>>(hidden);
    split_w_kernel<<<dim3(16, 32, 16), 256>>>(W_s1);
    router_kernel<<<NL * (NT / 64), 256>>>(hidden, W_r1, b_r1, W_r2, b_r2);
    topk_kernel<<<NL * 8, 256>>>();
    copy_kernel<<<NL * NK, 128>>>(s2, out);
    dim3 g(ND / 128, (NT - NK) / 128, NL);
    s1_gemm_cp<<<g, 256, SM_TOTAL>>>(b_s1, out);
}

// round 8
// speedup vs baseline: 1.5291x; 1.4739x over previous
#include <cuda_runtime.h>
#include <cuda_bf16.h>
#include <math.h>
#include <stdint.h>

#define NL 16
#define NT 2048
#define ND 2048
#define NR 128
#define NK 1024      // top-k capacity (T * 0.5)
#define BANDCAP 64
#define BAND_DELTA 5e-4f

// Scratch (no device allocation allowed -> __device__ globals)
__device__ float g_probs[NL * NT];
__device__ int   g_order[NL * NT];
__device__ int   g_bandcnt[NL];
__device__ int   g_band[NL * BANDCAP];

// Pre-split bf16 hi/lo scratch (Dekker split of fp32)
__device__ __nv_bfloat16 g_Hh[67108864];   // hidden hi  [l][t][d]
__device__ __nv_bfloat16 g_Hl[67108864];   // hidden lo
__device__ __nv_bfloat16 g_Wh[67108864];   // W_s1 hi, TRANSPOSED [l][e][d]
__device__ __nv_bfloat16 g_Wl[67108864];   // W_s1 lo
__device__ __nv_bfloat16 g_R1h[4194304];   // W_r1 hi, TRANSPOSED [l][r][d]
__device__ __nv_bfloat16 g_R1l[4194304];   // W_r1 lo

// ===========================================================================
// Helpers (sm_80-compatible PTX only)
// ===========================================================================
__device__ __forceinline__ uint32_t smem_u32(const void* p) {
    uint32_t a;
    asm("{ .reg .u64 t; cvta.to.shared.u64 t, %1; cvt.u32.u64 %0, t; }" : "=r"(a) : "l"(p));
    return a;
}
__device__ __forceinline__ void ldsm_x4(uint32_t* d, uint32_t addr) {
    asm volatile("ldmatrix.sync.aligned.m8n8.x4.shared.b16 {%0,%1,%2,%3}, [%4];"
                 : "=r"(d[0]), "=r"(d[1]), "=r"(d[2]), "=r"(d[3]) : "r"(addr));
}
__device__ __forceinline__ void mma_bf16(float* c, const uint32_t* a, uint32_t b0, uint32_t b1) {
    asm volatile(
        "mma.sync.aligned.m16n8k16.row.col.f32.bf16.bf16.f32 "
        "{%0,%1,%2,%3}, {%4,%5,%6,%7}, {%8,%9}, {%0,%1,%2,%3};"
        : "+f"(c[0]), "+f"(c[1]), "+f"(c[2]), "+f"(c[3])
        : "r"(a[0]), "r"(a[1]), "r"(a[2]), "r"(a[3]), "r"(b0), "r"(b1));
}
__device__ __forceinline__ void split2(float x, float y, uint32_t& h, uint32_t& l) {
    __nv_bfloat16 hx = __float2bfloat16_rn(x);
    __nv_bfloat16 hy = __float2bfloat16_rn(y);
    __nv_bfloat16 lx = __float2bfloat16_rn(x - __bfloat162float(hx));
    __nv_bfloat16 ly = __float2bfloat16_rn(y - __bfloat162float(hy));
    __nv_bfloat162 th = __halves2bfloat162(hx, hy);
    __nv_bfloat162 tl = __halves2bfloat162(lx, ly);
    h = *reinterpret_cast<uint32_t*>(&th);
    l = *reinterpret_cast<uint32_t*>(&tl);
}
#define CP16(d, s) asm volatile("cp.async.cg.shared.global [%0], [%1], 16;\n" :: "r"(d), "l"(s))
#define CPCOMMIT() asm volatile("cp.async.commit_group;\n" ::: "memory")
#define CPWAIT2()  asm volatile("cp.async.wait_group 2;\n" ::: "memory")

// ---------------------------------------------------------------------------
// Pre-split kernels
// ---------------------------------------------------------------------------
__global__ __launch_bounds__(256) void split_h_kernel(const float* __restrict__ h)
{
    size_t idx = ((size_t)blockIdx.x * 256 + threadIdx.x) * 4;
    float4 v = *(const float4*)(h + idx);
    uint32_t h0, l0, h1, l1;
    split2(v.x, v.y, h0, l0);
    split2(v.z, v.w, h1, l1);
    *(uint2*)&g_Hh[idx] = make_uint2(h0, h1);
    *(uint2*)&g_Hl[idx] = make_uint2(l0, l1);
}

// W_s1 [l][d][e] -> g_W{h,l} transposed [l][e][d]
__global__ __launch_bounds__(256) void split_w_kernel(const float* __restrict__ W)
{
    __shared__ float s[64][129];
    const int l = blockIdx.z, kb = blockIdx.y, eb = blockIdx.x;
    const int tid = threadIdx.x;
    const float* src = W + ((size_t)l * ND + kb * 64) * ND + eb * 128;
    #pragma unroll
    for (int i = 0; i < 8; i++) {
        int idx = tid + i * 256;
        int k = idx >> 5;
        int e4 = (idx & 31) * 4;
        float4 v = *(const float4*)(src + (size_t)k * ND + e4);
        s[k][e4] = v.x; s[k][e4 + 1] = v.y; s[k][e4 + 2] = v.z; s[k][e4 + 3] = v.w;
    }
    __syncthreads();
    const int e  = tid >> 1;
    const int kh = (tid & 1) * 32;
    uint32_t hw[16], lw[16];
    #pragma unroll
    for (int j = 0; j < 16; j++)
        split2(s[kh + 2 * j][e], s[kh + 2 * j + 1][e], hw[j], lw[j]);
    size_t doff = ((size_t)l * ND + eb * 128 + e) * ND + kb * 64 + kh;
    #pragma unroll
    for (int q = 0; q < 4; q++) {
        *(uint4*)&g_Wh[doff + q * 8] = make_uint4(hw[4*q], hw[4*q+1], hw[4*q+2], hw[4*q+3]);
        *(uint4*)&g_Wl[doff + q * 8] = make_uint4(lw[4*q], lw[4*q+1], lw[4*q+2], lw[4*q+3]);
    }
}

// W_r1 [l][d][r] -> g_R1{h,l} transposed [l][r][d]
__global__ __launch_bounds__(256) void split_r1_kernel(const float* __restrict__ W)
{
    __shared__ float s[64][129];
    const int l = blockIdx.y, kb = blockIdx.x;   // 64 d-rows per block
    const int tid = threadIdx.x;
    const float* src = W + ((size_t)l * ND + kb * 64) * NR;
    #pragma unroll
    for (int i = 0; i < 8; i++) {
        int idx = tid + i * 256;          // 2048 float4 = 64k x 128r
        int k  = idx >> 5;
        int r4 = (idx & 31) * 4;
        float4 v = *(const float4*)(src + (size_t)k * NR + r4);
        s[k][r4] = v.x; s[k][r4 + 1] = v.y; s[k][r4 + 2] = v.z; s[k][r4 + 3] = v.w;
    }
    __syncthreads();
    const int r  = tid >> 1;
    const int kh = (tid & 1) * 32;
    uint32_t hw[16], lw[16];
    #pragma unroll
    for (int j = 0; j < 16; j++)
        split2(s[kh + 2 * j][r], s[kh + 2 * j + 1][r], hw[j], lw[j]);
    size_t doff = ((size_t)l * NR + r) * ND + kb * 64 + kh;
    #pragma unroll
    for (int q = 0; q < 4; q++) {
        *(uint4*)&g_R1h[doff + q * 8] = make_uint4(hw[4*q], hw[4*q+1], hw[4*q+2], hw[4*q+3]);
        *(uint4*)&g_R1l[doff + q * 8] = make_uint4(lw[4*q], lw[4*q+1], lw[4*q+2], lw[4*q+3]);
    }
}

// ===========================================================================
// Shared GEMM-core macros (proven R5/R7 structure)
// ===========================================================================
#define KC       32
#define ASTRIDE  40
#define OFF_AL   10240
#define OFF_BH   20480
#define OFF_BL   30720
#define BUFB     40960

#define GEMM_ISSUE(cc, buf) do {                                                \
    uint32_t bb = sbase + (buf) * BUFB;                                         \
    const __nv_bfloat16* pah = aH + (cc) * KC;                                  \
    const __nv_bfloat16* pal = aL + (cc) * KC;                                  \
    const __nv_bfloat16* pbh = bH + (cc) * KC;                                  \
    const __nv_bfloat16* pbl = bL + (cc) * KC;                                  \
    CP16(bb + stsA,          pah); CP16(bb + stsA + 16,          pah + 8);      \
    CP16(bb + OFF_AL + stsA, pal); CP16(bb + OFF_AL + stsA + 16, pal + 8);      \
    CP16(bb + OFF_BH + stsA, pbh); CP16(bb + OFF_BH + stsA + 16, pbh + 8);      \
    CP16(bb + OFF_BL + stsA, pbl); CP16(bb + OFF_BL + stsA + 16, pbl + 8);      \
    CPCOMMIT();                                                                 \
} while (0)

#define GEMM_COMPUTE(buf) do {                                                  \
    const uint32_t bb = sbase + (buf) * BUFB;                                   \
    _Pragma("unroll")                                                           \
    for (int s = 0; s < 2; s++) {                                               \
        const int k0 = s * 16;                                                  \
        uint32_t ah[4][4], al[4][4], bh[2][4], bl[2][4];                        \
        const uint32_t a_ad = bb + ((m_base + frow) * ASTRIDE + k0 + fcol) * 2; \
        _Pragma("unroll")                                                       \
        for (int i = 0; i < 4; i++) {                                           \
            ldsm_x4(ah[i], a_ad + i * (16 * ASTRIDE * 2));                      \
            ldsm_x4(al[i], a_ad + OFF_AL + i * (16 * ASTRIDE * 2));             \
        }                                                                       \
        const uint32_t b_ad = bb + OFF_BH + ((n_base + frow) * ASTRIDE + k0 + fcol) * 2; \
        _Pragma("unroll")                                                       \
        for (int j = 0; j < 2; j++) {                                           \
            ldsm_x4(bh[j], b_ad + j * (16 * ASTRIDE * 2));                      \
            ldsm_x4(bl[j], b_ad + (OFF_BL - OFF_BH) + j * (16 * ASTRIDE * 2));  \
        }                                                                       \
        _Pragma("unroll")                                                       \
        for (int i = 0; i < 4; i++) {                                           \
            _Pragma("unroll")                                                   \
            for (int jj = 0; jj < 2; jj++) {                                    \
                _Pragma("unroll")                                               \
                for (int hi = 0; hi < 2; hi++) {                                \
                    const int g = jj * 2 + hi;                                  \
                    mma_bf16(acc[i][g], ah[i], bh[jj][hi], bh[jj][hi + 2]);     \
                    mma_bf16(acc[i][g], ah[i], bl[jj][hi], bl[jj][hi + 2]);     \
                    mma_bf16(acc[i][g], al[i], bh[jj][hi], bh[jj][hi + 2]);     \
                }                                                               \
            }                                                                   \
        }                                                                       \
    }                                                                           \
} while (0)

#define GEMM_PROLOG_BODY(NCHUNK)                                                \
    GEMM_ISSUE(0, 0); GEMM_ISSUE(1, 1); GEMM_ISSUE(2, 2);                       \
    for (int c = 0; c < (NCHUNK); c++) {                                        \
        CPWAIT2();                                                              \
        __syncthreads();                                                        \
        GEMM_COMPUTE(c & 3);                                                    \
        if (c + 3 < (NCHUNK)) GEMM_ISSUE(c + 3, (c + 3) & 3);                   \
    }

// ---------------------------------------------------------------------------
// Router GEMM on tensor cores (bf16 hi/lo x3): approx probs.
// CTA: 128 tokens x 128 R, K=2048. Same core as s1 GEMM.
// ---------------------------------------------------------------------------
#define RT_MISC  163840
#define RT_SM    167424   // misc: sB1 512 + sW2 512 + spart 2048

__global__ __launch_bounds__(256, 1) void router_mm(
    const float* __restrict__ b_r1,
    const float* __restrict__ W_r2,
    const float* __restrict__ b_r2)
{
    extern __shared__ char sm[];
    const int l   = blockIdx.y;
    const int t0  = blockIdx.x * 128;
    const int tid = threadIdx.x;
    const int w   = tid >> 5;
    const int lane = tid & 31;
    const uint32_t sbase = smem_u32(sm);

    float* sB1   = (float*)(sm + RT_MISC);
    float* sW2   = (float*)(sm + RT_MISC + 512);
    float* spart = (float*)(sm + RT_MISC + 1024);   // [4][128]
    if (tid < NR) {
        sB1[tid] = b_r1[l * NR + tid];
        sW2[tid] = W_r2[l * NR + tid];
    }
    __syncthreads();

    const int row = tid >> 1;
    const int kh  = (tid & 1) * 16;
    const __nv_bfloat16* aH = g_Hh + ((size_t)l * NT + t0 + row) * ND + kh;
    const __nv_bfloat16* aL = g_Hl + ((size_t)l * NT + t0 + row) * ND + kh;
    const __nv_bfloat16* bH = g_R1h + ((size_t)l * NR + row) * ND + kh;
    const __nv_bfloat16* bL = g_R1l + ((size_t)l * NR + row) * ND + kh;
    const uint32_t stsA = (uint32_t)(row * ASTRIDE + kh) * 2;

    const int wm = w & 1, wn = w >> 1;
    const int m_base = wm * 64, n_base = wn * 32;
    const int frow = lane & 15;
    const int fcol = (lane >> 4) * 8;

    float acc[4][4][4];
    #pragma unroll
    for (int i = 0; i < 4; i++)
        #pragma unroll
        for (int g = 0; g < 4; g++)
            #pragma unroll
            for (int e = 0; e < 4; e++) acc[i][g][e] = 0.f;

    GEMM_PROLOG_BODY(ND / KC)

    // epilogue: relu(acc + b1) . w2, reduce to per-token partial
    const int tq = lane >> 2;
    const int tr = lane & 3;
    #pragma unroll
    for (int i = 0; i < 4; i++) {
        float sa = 0.f, sb = 0.f;
        #pragma unroll
        for (int g = 0; g < 4; g++) {
            const int c0 = n_base + g * 8 + tr * 2;
            const float b0 = sB1[c0], b1v = sB1[c0 + 1];
            const float w0 = sW2[c0], w1v = sW2[c0 + 1];
            sa += fmaxf(acc[i][g][0] + b0, 0.f) * w0 + fmaxf(acc[i][g][1] + b1v, 0.f) * w1v;
            sb += fmaxf(acc[i][g][2] + b0, 0.f) * w0 + fmaxf(acc[i][g][3] + b1v, 0.f) * w1v;
        }
        sa += __shfl_down_sync(0xffffffffu, sa, 2, 4);
        sa += __shfl_down_sync(0xffffffffu, sa, 1, 4);
        sb += __shfl_down_sync(0xffffffffu, sb, 2, 4);
        sb += __shfl_down_sync(0xffffffffu, sb, 1, 4);
        if (tr == 0) {
            spart[wn * 128 + m_base + i * 16 + tq]     = sa;
            spart[wn * 128 + m_base + i * 16 + tq + 8] = sb;
        }
    }
    __syncthreads();

    if (tid < 128) {
        float logit = spart[tid] + spart[128 + tid] + spart[256 + tid] + spart[384 + tid]
                    + b_r2[l];
        g_probs[l * NT + t0 + tid] = 1.0f / (1.0f + expf(-logit));
    }
}

// ---------------------------------------------------------------------------
// Top-K via exhaustive rank — 8 blocks/layer, 1 token/thread
// ---------------------------------------------------------------------------
__global__ __launch_bounds__(256) void topk_kernel()
{
    __shared__ float sp[NT];
    const int l   = blockIdx.x >> 3;
    const int seg = blockIdx.x & 7;
    for (int i = threadIdx.x; i < NT; i += 256) sp[i] = g_probs[l * NT + i];
    __syncthreads();

    const int t = seg * 256 + threadIdx.x;
    const float p = sp[t];
    int rank = 0;
    #pragma unroll 8
    for (int j = 0; j < NT; j++) {
        float q = sp[j];
        rank += (q > p) || (q == p && j < t);
    }
    g_order[l * NT + rank] = t;
}

// ---------------------------------------------------------------------------
// Find tokens within BAND_DELTA of the K-th prob (boundary band)
// ---------------------------------------------------------------------------
__global__ __launch_bounds__(256) void band_find_kernel()
{
    __shared__ int cnt;
    __shared__ float vK;
    const int l = blockIdx.x;
    if (threadIdx.x == 0) {
        cnt = 0;
        vK = g_probs[l * NT + g_order[l * NT + NK - 1]];
    }
    __syncthreads();
    for (int t = threadIdx.x; t < NT; t += 256) {
        float p = g_probs[l * NT + t];
        if (fabsf(p - vK) <= BAND_DELTA) {
            int i = atomicAdd(&cnt, 1);
            if (i < BANDCAP) g_band[l * BANDCAP + i] = t;
        }
    }
    __syncthreads();
    if (threadIdx.x == 0) g_bandcnt[l] = cnt < BANDCAP ? cnt : BANDCAP;
}

// ---------------------------------------------------------------------------
// Exact fp32 recompute of band tokens' probs (few per layer)
// ---------------------------------------------------------------------------
__global__ __launch_bounds__(128) void exact_fix_kernel(
    const float* __restrict__ hidden,
    const float* __restrict__ W_r1,
    const float* __restrict__ b_r1,
    const float* __restrict__ W_r2,
    const float* __restrict__ b_r2)
{
    const int i = blockIdx.x, l = blockIdx.y;
    if (i >= g_bandcnt[l]) return;
    const int t = g_band[l * BANDCAP + i];
    const int r = threadIdx.x;

    const float* h = hidden + ((size_t)l * NT + t) * ND;
    const float* w = W_r1 + (size_t)l * ND * NR + r;
    float acc = 0.f;
    #pragma unroll 8
    for (int d = 0; d < ND; d++) acc += h[d] * w[(size_t)d * NR];

    float v = fmaxf(acc + b_r1[l * NR + r], 0.f) * W_r2[l * NR + r];

    __shared__ float red[128];
    red[r] = v;
    __syncthreads();
    #pragma unroll
    for (int s = 64; s > 0; s >>= 1) {
        if (r < s) red[r] += red[r + s];
        __syncthreads();
    }
    if (r == 0) {
        float logit = red[0] + b_r2[l];
        g_probs[l * NT + t] = 1.0f / (1.0f + expf(-logit));
    }
}

// ---------------------------------------------------------------------------
// Copy s2 rows (proven)
// ---------------------------------------------------------------------------
__global__ __launch_bounds__(128) void copy_kernel(
    const float* __restrict__ s2, float* __restrict__ out)
{
    const int l = blockIdx.x >> 10;
    const int i = blockIdx.x & (NK - 1);
    const int t = g_order[l * NT + i];
    const float4* src = (const float4*)(s2 + ((size_t)l * NT + t) * ND);
    float4*       dst = (float4*)(out + ((size_t)l * NT + t) * ND);
    #pragma unroll
    for (int j = threadIdx.x; j < ND / 4; j += 128) dst[j] = src[j];
}

// ---------------------------------------------------------------------------
// s1 GEMM (R7 structure, unchanged): HMMA bf16 hi/lo x3 via cp.async
// ---------------------------------------------------------------------------
#define SM_ROWS  163840
#define SM_TOTAL 164352

__global__ __launch_bounds__(256, 1) void s1_gemm_cp(
    const float* __restrict__ b_s1,
    float* __restrict__ out)
{
    extern __shared__ char sm[];
    const int l   = blockIdx.z;
    const int n0  = blockIdx.x * 128;
    const int r0  = blockIdx.y * 128;
    const int tid = threadIdx.x;
    const int w   = tid >> 5;
    const int lane = tid & 31;
    const uint32_t sbase = smem_u32(sm);

    int* srows = (int*)(sm + SM_ROWS);
    if (tid < 128) srows[tid] = g_order[l * NT + NK + r0 + tid];
    __syncthreads();

    const int row = tid >> 1;
    const int kh  = (tid & 1) * 16;
    const __nv_bfloat16* aH = g_Hh + ((size_t)l * NT + srows[row]) * ND + kh;
    const __nv_bfloat16* aL = g_Hl + ((size_t)l * NT + srows[row]) * ND + kh;
    const __nv_bfloat16* bH = g_Wh + ((size_t)l * ND + n0 + row) * ND + kh;
    const __nv_bfloat16* bL = g_Wl + ((size_t)l * ND + n0 + row) * ND + kh;
    const uint32_t stsA = (uint32_t)(row * ASTRIDE + kh) * 2;

    const int wm = w & 1, wn = w >> 1;
    const int m_base = wm * 64, n_base = wn * 32;
    const int frow = lane & 15;
    const int fcol = (lane >> 4) * 8;

    float acc[4][4][4];
    #pragma unroll
    for (int i = 0; i < 4; i++)
        #pragma unroll
        for (int g = 0; g < 4; g++)
            #pragma unroll
            for (int e = 0; e < 4; e++) acc[i][g][e] = 0.f;

    GEMM_PROLOG_BODY(ND / KC)

    const int tq = lane >> 2;
    const int tr = lane & 3;
    #pragma unroll
    for (int g = 0; g < 4; g++) {
        const int col = n_base + g * 8 + tr * 2;
        const float bx = __ldg(b_s1 + l * ND + n0 + col);
        const float by = __ldg(b_s1 + l * ND + n0 + col + 1);
        #pragma unroll
        for (int i = 0; i < 4; i++) {
            const int rl = m_base + i * 16 + tq;
            float* o0 = out + ((size_t)l * NT + srows[rl])     * ND + n0 + col;
            float* o1 = out + ((size_t)l * NT + srows[rl + 8]) * ND + n0 + col;
            *(float2*)o0 = make_float2(acc[i][g][0] + bx, acc[i][g][1] + by);
            *(float2*)o1 = make_float2(acc[i][g][2] + bx, acc[i][g][3] + by);
        }
    }
}

// ---------------------------------------------------------------------------
extern "C" void kernel_launch(void* const* d_in, const int* in_sizes, int n_in,
                              void* d_out, int out_size)
{
    const float* hidden = (const float*)d_in[0];
    const float* s2     = (const float*)d_in[1];
    const float* W_r1   = (const float*)d_in[2];
    const float* b_r1   = (const float*)d_in[3];
    const float* W_r2   = (const float*)d_in[4];
    const float* b_r2   = (const float*)d_in[5];
    const float* W_s1   = (const float*)d_in[6];
    const float* b_s1   = (const float*)d_in[7];
    float* out = (float*)d_out;

    static bool attr_done = false;
    if (!attr_done) {
        cudaFuncSetAttribute(s1_gemm_cp, cudaFuncAttributeMaxDynamicSharedMemorySize, SM_TOTAL);
        cudaFuncSetAttribute(router_mm, cudaFuncAttributeMaxDynamicSharedMemorySize, RT_SM);
        attr_done = true;
    }

    split_h_kernel<<<65536, 256>>>(hidden);
    split_w_kernel<<<dim3(16, 32, 16), 256>>>(W_s1);
    split_r1_kernel<<<dim3(32, 16), 256>>>(W_r1);

    router_mm<<<dim3(16, 16), 256, RT_SM>>>(b_r1, W_r2, b_r2);
    topk_kernel<<<NL * 8, 256>>>();
    band_find_kernel<<<NL, 256>>>();
    exact_fix_kernel<<<dim3(BANDCAP, NL), 128>>>(hidden, W_r1, b_r1, W_r2, b_r2);
    topk_kernel<<<NL * 8, 256>>>();

    copy_kernel<<<NL * NK, 128>>>(s2, out);
    dim3 g(ND / 128, (NT - NK) / 128, NL);
    s1_gemm_cp<<<g, 256, SM_TOTAL>>>(b_s1, out);
}

// round 9
// speedup vs baseline: 1.9379x; 1.2673x over previous
#include <cuda_runtime.h>
#include <cuda_fp16.h>
#include <math.h>
#include <stdint.h>

#define NL 16
#define NT 2048
#define ND 2048
#define NR 128
#define NK 1024      // top-k capacity (T * 0.5)
#define BANDCAP 64
#define BAND_DELTA 5e-4f

// Scratch (no device allocation allowed -> __device__ globals)
__device__ float g_probs[NL * NT];
__device__ int   g_order[NL * NT];
__device__ int   g_bandcnt[NL];
__device__ int   g_band[NL * BANDCAP];

// Pre-split fp16 hi/lo scratch (Dekker split of fp32)
__device__ __half g_Hh[67108864];   // hidden hi  [l][t][d]   (= RN16(hidden))
__device__ __half g_Hl[67108864];   // hidden lo
__device__ __half g_Wh[67108864];   // W_s1 hi, TRANSPOSED [l][e][d]
__device__ __half g_Wl[67108864];   // W_s1 lo
__device__ __half g_R1h[4194304];   // W_r1 hi, TRANSPOSED [l][r][d]
__device__ __half g_R1l[4194304];   // W_r1 lo

// ===========================================================================
// Helpers (sm_80-compatible PTX only)
// ===========================================================================
__device__ __forceinline__ uint32_t smem_u32(const void* p) {
    uint32_t a;
    asm("{ .reg .u64 t; cvta.to.shared.u64 t, %1; cvt.u32.u64 %0, t; }" : "=r"(a) : "l"(p));
    return a;
}
__device__ __forceinline__ void ldsm_x4(uint32_t* d, uint32_t addr) {
    asm volatile("ldmatrix.sync.aligned.m8n8.x4.shared.b16 {%0,%1,%2,%3}, [%4];"
                 : "=r"(d[0]), "=r"(d[1]), "=r"(d[2]), "=r"(d[3]) : "r"(addr));
}
__device__ __forceinline__ void mma_f16(float* c, const uint32_t* a, uint32_t b0, uint32_t b1) {
    asm volatile(
        "mma.sync.aligned.m16n8k16.row.col.f32.f16.f16.f32 "
        "{%0,%1,%2,%3}, {%4,%5,%6,%7}, {%8,%9}, {%0,%1,%2,%3};"
        : "+f"(c[0]), "+f"(c[1]), "+f"(c[2]), "+f"(c[3])
        : "r"(a[0]), "r"(a[1]), "r"(a[2]), "r"(a[3]), "r"(b0), "r"(b1));
}
// fp16 Dekker split of two fp32 -> packed hi word + lo word
__device__ __forceinline__ void split2(float x, float y, uint32_t& h, uint32_t& l) {
    __half hx = __float2half_rn(x);
    __half hy = __float2half_rn(y);
    __half lx = __float2half_rn(x - __half2float(hx));
    __half ly = __float2half_rn(y - __half2float(hy));
    __half2 th = __halves2half2(hx, hy);
    __half2 tl = __halves2half2(lx, ly);
    h = *reinterpret_cast<uint32_t*>(&th);
    l = *reinterpret_cast<uint32_t*>(&tl);
}
#define CP16(d, s) asm volatile("cp.async.cg.shared.global [%0], [%1], 16;\n" :: "r"(d), "l"(s))
#define CPCOMMIT() asm volatile("cp.async.commit_group;\n" ::: "memory")
#define CPWAIT2()  asm volatile("cp.async.wait_group 2;\n" ::: "memory")

// ---------------------------------------------------------------------------
// Pre-split kernels
// ---------------------------------------------------------------------------
__global__ __launch_bounds__(256) void split_h_kernel(const float* __restrict__ h)
{
    size_t idx = ((size_t)blockIdx.x * 256 + threadIdx.x) * 4;
    float4 v = *(const float4*)(h + idx);
    uint32_t h0, l0, h1, l1;
    split2(v.x, v.y, h0, l0);
    split2(v.z, v.w, h1, l1);
    *(uint2*)&g_Hh[idx] = make_uint2(h0, h1);
    *(uint2*)&g_Hl[idx] = make_uint2(l0, l1);
}

// W_s1 [l][d][e] -> g_W{h,l} transposed [l][e][d]
__global__ __launch_bounds__(256) void split_w_kernel(const float* __restrict__ W)
{
    __shared__ float s[64][129];
    const int l = blockIdx.z, kb = blockIdx.y, eb = blockIdx.x;
    const int tid = threadIdx.x;
    const float* src = W + ((size_t)l * ND + kb * 64) * ND + eb * 128;
    #pragma unroll
    for (int i = 0; i < 8; i++) {
        int idx = tid + i * 256;
        int k = idx >> 5;
        int e4 = (idx & 31) * 4;
        float4 v = *(const float4*)(src + (size_t)k * ND + e4);
        s[k][e4] = v.x; s[k][e4 + 1] = v.y; s[k][e4 + 2] = v.z; s[k][e4 + 3] = v.w;
    }
    __syncthreads();
    const int e  = tid >> 1;
    const int kh = (tid & 1) * 32;
    uint32_t hw[16], lw[16];
    #pragma unroll
    for (int j = 0; j < 16; j++)
        split2(s[kh + 2 * j][e], s[kh + 2 * j + 1][e], hw[j], lw[j]);
    size_t doff = ((size_t)l * ND + eb * 128 + e) * ND + kb * 64 + kh;
    #pragma unroll
    for (int q = 0; q < 4; q++) {
        *(uint4*)&g_Wh[doff + q * 8] = make_uint4(hw[4*q], hw[4*q+1], hw[4*q+2], hw[4*q+3]);
        *(uint4*)&g_Wl[doff + q * 8] = make_uint4(lw[4*q], lw[4*q+1], lw[4*q+2], lw[4*q+3]);
    }
}

// W_r1 [l][d][r] -> g_R1{h,l} transposed [l][r][d]
__global__ __launch_bounds__(256) void split_r1_kernel(const float* __restrict__ W)
{
    __shared__ float s[64][129];
    const int l = blockIdx.y, kb = blockIdx.x;
    const int tid = threadIdx.x;
    const float* src = W + ((size_t)l * ND + kb * 64) * NR;
    #pragma unroll
    for (int i = 0; i < 8; i++) {
        int idx = tid + i * 256;
        int k  = idx >> 5;
        int r4 = (idx & 31) * 4;
        float4 v = *(const float4*)(src + (size_t)k * NR + r4);
        s[k][r4] = v.x; s[k][r4 + 1] = v.y; s[k][r4 + 2] = v.z; s[k][r4 + 3] = v.w;
    }
    __syncthreads();
    const int r  = tid >> 1;
    const int kh = (tid & 1) * 32;
    uint32_t hw[16], lw[16];
    #pragma unroll
    for (int j = 0; j < 16; j++)
        split2(s[kh + 2 * j][r], s[kh + 2 * j + 1][r], hw[j], lw[j]);
    size_t doff = ((size_t)l * NR + r) * ND + kb * 64 + kh;
    #pragma unroll
    for (int q = 0; q < 4; q++) {
        *(uint4*)&g_R1h[doff + q * 8] = make_uint4(hw[4*q], hw[4*q+1], hw[4*q+2], hw[4*q+3]);
        *(uint4*)&g_R1l[doff + q * 8] = make_uint4(lw[4*q], lw[4*q+1], lw[4*q+2], lw[4*q+3]);
    }
}

// ===========================================================================
// Common tile constants
// ===========================================================================
#define KC       32
#define ASTRIDE  40

// ---------------------------------------------------------------------------
// Router GEMM on tensor cores (fp16 hi/lo x3 products): approx probs.
// CTA: 128 tokens x 128 R, K=2048. 4 smem arrays per buffer.
// ---------------------------------------------------------------------------
#define R_OFF_AL 10240
#define R_OFF_BH 20480
#define R_OFF_BL 30720
#define R_BUFB   40960
#define RT_MISC  163840
#define RT_SM    167424

__global__ __launch_bounds__(256, 1) void router_mm(
    const float* __restrict__ b_r1,
    const float* __restrict__ W_r2,
    const float* __restrict__ b_r2)
{
    extern __shared__ char sm[];
    const int l   = blockIdx.y;
    const int t0  = blockIdx.x * 128;
    const int tid = threadIdx.x;
    const int w   = tid >> 5;
    const int lane = tid & 31;
    const uint32_t sbase = smem_u32(sm);

    float* sB1   = (float*)(sm + RT_MISC);
    float* sW2   = (float*)(sm + RT_MISC + 512);
    float* spart = (float*)(sm + RT_MISC + 1024);
    if (tid < NR) {
        sB1[tid] = b_r1[l * NR + tid];
        sW2[tid] = W_r2[l * NR + tid];
    }
    __syncthreads();

    const int row = tid >> 1;
    const int kh  = (tid & 1) * 16;
    const __half* aH = g_Hh + ((size_t)l * NT + t0 + row) * ND + kh;
    const __half* aL = g_Hl + ((size_t)l * NT + t0 + row) * ND + kh;
    const __half* bH = g_R1h + ((size_t)l * NR + row) * ND + kh;
    const __half* bL = g_R1l + ((size_t)l * NR + row) * ND + kh;
    const uint32_t stsA = (uint32_t)(row * ASTRIDE + kh) * 2;

    const int wm = w & 1, wn = w >> 1;
    const int m_base = wm * 64, n_base = wn * 32;
    const int frow = lane & 15;
    const int fcol = (lane >> 4) * 8;

    float acc[4][4][4];
    #pragma unroll
    for (int i = 0; i < 4; i++)
        #pragma unroll
        for (int g = 0; g < 4; g++)
            #pragma unroll
            for (int e = 0; e < 4; e++) acc[i][g][e] = 0.f;

    #define R_ISSUE(cc, buf) do {                                               \
        uint32_t bb = sbase + (buf) * R_BUFB;                                   \
        const __half* pah = aH + (cc) * KC;                                     \
        const __half* pal = aL + (cc) * KC;                                     \
        const __half* pbh = bH + (cc) * KC;                                     \
        const __half* pbl = bL + (cc) * KC;                                     \
        CP16(bb + stsA,            pah); CP16(bb + stsA + 16,            pah + 8); \
        CP16(bb + R_OFF_AL + stsA, pal); CP16(bb + R_OFF_AL + stsA + 16, pal + 8); \
        CP16(bb + R_OFF_BH + stsA, pbh); CP16(bb + R_OFF_BH + stsA + 16, pbh + 8); \
        CP16(bb + R_OFF_BL + stsA, pbl); CP16(bb + R_OFF_BL + stsA + 16, pbl + 8); \
        CPCOMMIT();                                                             \
    } while (0)

    #define R_COMPUTE(buf) do {                                                 \
        const uint32_t bb = sbase + (buf) * R_BUFB;                             \
        _Pragma("unroll")                                                       \
        for (int s = 0; s < 2; s++) {                                           \
            const int k0 = s * 16;                                              \
            uint32_t ah[4][4], al[4][4], bh[2][4], bl[2][4];                    \
            const uint32_t a_ad = bb + ((m_base + frow) * ASTRIDE + k0 + fcol) * 2; \
            _Pragma("unroll")                                                   \
            for (int i = 0; i < 4; i++) {                                       \
                ldsm_x4(ah[i], a_ad + i * (16 * ASTRIDE * 2));                  \
                ldsm_x4(al[i], a_ad + R_OFF_AL + i * (16 * ASTRIDE * 2));       \
            }                                                                   \
            const uint32_t b_ad = bb + R_OFF_BH + ((n_base + frow) * ASTRIDE + k0 + fcol) * 2; \
            _Pragma("unroll")                                                   \
            for (int j = 0; j < 2; j++) {                                       \
                ldsm_x4(bh[j], b_ad + j * (16 * ASTRIDE * 2));                  \
                ldsm_x4(bl[j], b_ad + (R_OFF_BL - R_OFF_BH) + j * (16 * ASTRIDE * 2)); \
            }                                                                   \
            _Pragma("unroll")                                                   \
            for (int i = 0; i < 4; i++) {                                       \
                _Pragma("unroll")                                               \
                for (int jj = 0; jj < 2; jj++) {                                \
                    _Pragma("unroll")                                           \
                    for (int hi = 0; hi < 2; hi++) {                            \
                        const int g = jj * 2 + hi;                              \
                        mma_f16(acc[i][g], ah[i], bh[jj][hi], bh[jj][hi + 2]);  \
                        mma_f16(acc[i][g], ah[i], bl[jj][hi], bl[jj][hi + 2]);  \
                        mma_f16(acc[i][g], al[i], bh[jj][hi], bh[jj][hi + 2]);  \
                    }                                                           \
                }                                                               \
            }                                                                   \
        }                                                                       \
    } while (0)

    R_ISSUE(0, 0); R_ISSUE(1, 1); R_ISSUE(2, 2);
    for (int c = 0; c < ND / KC; c++) {
        CPWAIT2();
        __syncthreads();
        R_COMPUTE(c & 3);
        if (c + 3 < ND / KC) R_ISSUE(c + 3, (c + 3) & 3);
    }

    // epilogue: relu(acc + b1) . w2, reduce to per-token partial
    const int tq = lane >> 2;
    const int tr = lane & 3;
    #pragma unroll
    for (int i = 0; i < 4; i++) {
        float sa = 0.f, sb = 0.f;
        #pragma unroll
        for (int g = 0; g < 4; g++) {
            const int c0 = n_base + g * 8 + tr * 2;
            const float b0 = sB1[c0], b1v = sB1[c0 + 1];
            const float w0 = sW2[c0], w1v = sW2[c0 + 1];
            sa += fmaxf(acc[i][g][0] + b0, 0.f) * w0 + fmaxf(acc[i][g][1] + b1v, 0.f) * w1v;
            sb += fmaxf(acc[i][g][2] + b0, 0.f) * w0 + fmaxf(acc[i][g][3] + b1v, 0.f) * w1v;
        }
        sa += __shfl_down_sync(0xffffffffu, sa, 2, 4);
        sa += __shfl_down_sync(0xffffffffu, sa, 1, 4);
        sb += __shfl_down_sync(0xffffffffu, sb, 2, 4);
        sb += __shfl_down_sync(0xffffffffu, sb, 1, 4);
        if (tr == 0) {
            spart[wn * 128 + m_base + i * 16 + tq]     = sa;
            spart[wn * 128 + m_base + i * 16 + tq + 8] = sb;
        }
    }
    __syncthreads();

    if (tid < 128) {
        float logit = spart[tid] + spart[128 + tid] + spart[256 + tid] + spart[384 + tid]
                    + b_r2[l];
        g_probs[l * NT + t0 + tid] = 1.0f / (1.0f + expf(-logit));
    }
}

// ---------------------------------------------------------------------------
// Top-K via exhaustive rank — 8 blocks/layer, 1 token/thread
// ---------------------------------------------------------------------------
__global__ __launch_bounds__(256) void topk_kernel()
{
    __shared__ float sp[NT];
    const int l   = blockIdx.x >> 3;
    const int seg = blockIdx.x & 7;
    for (int i = threadIdx.x; i < NT; i += 256) sp[i] = g_probs[l * NT + i];
    __syncthreads();

    const int t = seg * 256 + threadIdx.x;
    const float p = sp[t];
    int rank = 0;
    #pragma unroll 8
    for (int j = 0; j < NT; j++) {
        float q = sp[j];
        rank += (q > p) || (q == p && j < t);
    }
    g_order[l * NT + rank] = t;
}

// ---------------------------------------------------------------------------
// Find tokens within BAND_DELTA of the K-th prob
// ---------------------------------------------------------------------------
__global__ __launch_bounds__(256) void band_find_kernel()
{
    __shared__ int cnt;
    __shared__ float vK;
    const int l = blockIdx.x;
    if (threadIdx.x == 0) {
        cnt = 0;
        vK = g_probs[l * NT + g_order[l * NT + NK - 1]];
    }
    __syncthreads();
    for (int t = threadIdx.x; t < NT; t += 256) {
        float p = g_probs[l * NT + t];
        if (fabsf(p - vK) <= BAND_DELTA) {
            int i = atomicAdd(&cnt, 1);
            if (i < BANDCAP) g_band[l * BANDCAP + i] = t;
        }
    }
    __syncthreads();
    if (threadIdx.x == 0) g_bandcnt[l] = cnt < BANDCAP ? cnt : BANDCAP;
}

// ---------------------------------------------------------------------------
// Exact fp32 recompute of band tokens' probs
// ---------------------------------------------------------------------------
__global__ __launch_bounds__(128) void exact_fix_kernel(
    const float* __restrict__ hidden,
    const float* __restrict__ W_r1,
    const float* __restrict__ b_r1,
    const float* __restrict__ W_r2,
    const float* __restrict__ b_r2)
{
    const int i = blockIdx.x, l = blockIdx.y;
    if (i >= g_bandcnt[l]) return;
    const int t = g_band[l * BANDCAP + i];
    const int r = threadIdx.x;

    const float* h = hidden + ((size_t)l * NT + t) * ND;
    const float* w = W_r1 + (size_t)l * ND * NR + r;
    float acc = 0.f;
    #pragma unroll 8
    for (int d = 0; d < ND; d++) acc += h[d] * w[(size_t)d * NR];

    float v = fmaxf(acc + b_r1[l * NR + r], 0.f) * W_r2[l * NR + r];

    __shared__ float red[128];
    red[r] = v;
    __syncthreads();
    #pragma unroll
    for (int s = 64; s > 0; s >>= 1) {
        if (r < s) red[r] += red[r + s];
        __syncthreads();
    }
    if (r == 0) {
        float logit = red[0] + b_r2[l];
        g_probs[l * NT + t] = 1.0f / (1.0f + expf(-logit));
    }
}

// ---------------------------------------------------------------------------
// Copy s2 rows (proven)
// ---------------------------------------------------------------------------
__global__ __launch_bounds__(128) void copy_kernel(
    const float* __restrict__ s2, float* __restrict__ out)
{
    const int l = blockIdx.x >> 10;
    const int i = blockIdx.x & (NK - 1);
    const int t = g_order[l * NT + i];
    const float4* src = (const float4*)(s2 + ((size_t)l * NT + t) * ND);
    float4*       dst = (float4*)(out + ((size_t)l * NT + t) * ND);
    #pragma unroll
    for (int j = threadIdx.x; j < ND / 4; j += 128) dst[j] = src[j];
}

// ---------------------------------------------------------------------------
// s1 GEMM: fp16 HMMA, 2 products (Ah*Bh + Ah*Bl; A single-rounded fp16).
// CTA 128(M, gathered) x 128(N), K-chunk 32, 4-deep cp.async pipeline.
// Per buffer: Ah / Bh / Bl, 10240 B each = 30720 B; 4 buffers = 122880.
// ---------------------------------------------------------------------------
#define S_OFF_BH 10240
#define S_OFF_BL 20480
#define S_BUFB   30720
#define S_ROWS   122880
#define S_SM     123392

__global__ __launch_bounds__(256, 1) void s1_gemm_cp(
    const float* __restrict__ b_s1,
    float* __restrict__ out)
{
    extern __shared__ char sm[];
    const int l   = blockIdx.z;
    const int n0  = blockIdx.x * 128;
    const int r0  = blockIdx.y * 128;
    const int tid = threadIdx.x;
    const int w   = tid >> 5;
    const int lane = tid & 31;
    const uint32_t sbase = smem_u32(sm);

    int* srows = (int*)(sm + S_ROWS);
    if (tid < 128) srows[tid] = g_order[l * NT + NK + r0 + tid];
    __syncthreads();

    const int row = tid >> 1;
    const int kh  = (tid & 1) * 16;
    const __half* aH = g_Hh + ((size_t)l * NT + srows[row]) * ND + kh;
    const __half* bH = g_Wh + ((size_t)l * ND + n0 + row) * ND + kh;
    const __half* bL = g_Wl + ((size_t)l * ND + n0 + row) * ND + kh;
    const uint32_t stsA = (uint32_t)(row * ASTRIDE + kh) * 2;

    const int wm = w & 1, wn = w >> 1;
    const int m_base = wm * 64, n_base = wn * 32;
    const int frow = lane & 15;
    const int fcol = (lane >> 4) * 8;

    float acc[4][4][4];
    #pragma unroll
    for (int i = 0; i < 4; i++)
        #pragma unroll
        for (int g = 0; g < 4; g++)
            #pragma unroll
            for (int e = 0; e < 4; e++) acc[i][g][e] = 0.f;

    #define S_ISSUE(cc, buf) do {                                               \
        uint32_t bb = sbase + (buf) * S_BUFB;                                   \
        const __half* pah = aH + (cc) * KC;                                     \
        const __half* pbh = bH + (cc) * KC;                                     \
        const __half* pbl = bL + (cc) * KC;                                     \
        CP16(bb + stsA,            pah); CP16(bb + stsA + 16,            pah + 8); \
        CP16(bb + S_OFF_BH + stsA, pbh); CP16(bb + S_OFF_BH + stsA + 16, pbh + 8); \
        CP16(bb + S_OFF_BL + stsA, pbl); CP16(bb + S_OFF_BL + stsA + 16, pbl + 8); \
        CPCOMMIT();                                                             \
    } while (0)

    #define S_COMPUTE(buf) do {                                                 \
        const uint32_t bb = sbase + (buf) * S_BUFB;                             \
        _Pragma("unroll")                                                       \
        for (int s = 0; s < 2; s++) {                                           \
            const int k0 = s * 16;                                              \
            uint32_t ah[4][4], bh[2][4], bl[2][4];                              \
            const uint32_t a_ad = bb + ((m_base + frow) * ASTRIDE + k0 + fcol) * 2; \
            _Pragma("unroll")                                                   \
            for (int i = 0; i < 4; i++)                                         \
                ldsm_x4(ah[i], a_ad + i * (16 * ASTRIDE * 2));                  \
            const uint32_t b_ad = bb + S_OFF_BH + ((n_base + frow) * ASTRIDE + k0 + fcol) * 2; \
            _Pragma("unroll")                                                   \
            for (int j = 0; j < 2; j++) {                                       \
                ldsm_x4(bh[j], b_ad + j * (16 * ASTRIDE * 2));                  \
                ldsm_x4(bl[j], b_ad + (S_OFF_BL - S_OFF_BH) + j * (16 * ASTRIDE * 2)); \
            }                                                                   \
            _Pragma("unroll")                                                   \
            for (int i = 0; i < 4; i++) {                                       \
                _Pragma("unroll")                                               \
                for (int jj = 0; jj < 2; jj++) {                                \
                    _Pragma("unroll")                                           \
                    for (int hi = 0; hi < 2; hi++) {                            \
                        const int g = jj * 2 + hi;                              \
                        mma_f16(acc[i][g], ah[i], bh[jj][hi], bh[jj][hi + 2]);  \
                        mma_f16(acc[i][g], ah[i], bl[jj][hi], bl[jj][hi + 2]);  \
                    }                                                           \
                }                                                               \
            }                                                                   \
        }                                                                       \
    } while (0)

    S_ISSUE(0, 0); S_ISSUE(1, 1); S_ISSUE(2, 2);
    for (int c = 0; c < ND / KC; c++) {
        CPWAIT2();
        __syncthreads();
        S_COMPUTE(c & 3);
        if (c + 3 < ND / KC) S_ISSUE(c + 3, (c + 3) & 3);
    }

    const int tq = lane >> 2;
    const int tr = lane & 3;
    #pragma unroll
    for (int g = 0; g < 4; g++) {
        const int col = n_base + g * 8 + tr * 2;
        const float bx = __ldg(b_s1 + l * ND + n0 + col);
        const float by = __ldg(b_s1 + l * ND + n0 + col + 1);
        #pragma unroll
        for (int i = 0; i < 4; i++) {
            const int rl = m_base + i * 16 + tq;
            float* o0 = out + ((size_t)l * NT + srows[rl])     * ND + n0 + col;
            float* o1 = out + ((size_t)l * NT + srows[rl + 8]) * ND + n0 + col;
            *(float2*)o0 = make_float2(acc[i][g][0] + bx, acc[i][g][1] + by);
            *(float2*)o1 = make_float2(acc[i][g][2] + bx, acc[i][g][3] + by);
        }
    }
}

// ---------------------------------------------------------------------------
extern "C" void kernel_launch(void* const* d_in, const int* in_sizes, int n_in,
                              void* d_out, int out_size)
{
    const float* hidden = (const float*)d_in[0];
    const float* s2     = (const float*)d_in[1];
    const float* W_r1   = (const float*)d_in[2];
    const float* b_r1   = (const float*)d_in[3];
    const float* W_r2   = (const float*)d_in[4];
    const float* b_r2   = (const float*)d_in[5];
    const float* W_s1   = (const float*)d_in[6];
    const float* b_s1   = (const float*)d_in[7];
    float* out = (float*)d_out;

    static bool attr_done = false;
    if (!attr_done) {
        cudaFuncSetAttribute(s1_gemm_cp, cudaFuncAttributeMaxDynamicSharedMemorySize, S_SM);
        cudaFuncSetAttribute(router_mm, cudaFuncAttributeMaxDynamicSharedMemorySize, RT_SM);
        attr_done = true;
    }

    split_h_kernel<<<65536, 256>>>(hidden);
    split_w_kernel<<<dim3(16, 32, 16), 256>>>(W_s1);
    split_r1_kernel<<<dim3(32, 16), 256>>>(W_r1);

    router_mm<<<dim3(16, 16), 256, RT_SM>>>(b_r1, W_r2, b_r2);
    topk_kernel<<<NL * 8, 256>>>();
    band_find_kernel<<<NL, 256>>>();
    exact_fix_kernel<<<dim3(BANDCAP, NL), 128>>>(hidden, W_r1, b_r1, W_r2, b_r2);
    topk_kernel<<<NL * 8, 256>>>();

    copy_kernel<<<NL * NK, 128>>>(s2, out);
    dim3 g(ND / 128, (NT - NK) / 128, NL);
    s1_gemm_cp<<<g, 256, S_SM>>>(b_s1, out);
}

// round 11
// speedup vs baseline: 2.2076x; 1.1392x over previous
#include <cuda_runtime.h>
#include <cuda_fp16.h>
#include <math.h>
#include <stdint.h>

#define NL 16
#define NT 2048
#define ND 2048
#define NR 128
#define NK 1024      // top-k capacity (T * 0.5)
#define BANDCAP 64
#define BAND_DELTA 5e-4f

// Scratch (no device allocation allowed -> __device__ globals)
__device__ float g_probs[NL * NT];
__device__ int   g_order[NL * NT];
__device__ int   g_bandcnt[NL];
__device__ int   g_band[NL * BANDCAP];

// Pre-split fp16 hi/lo scratch (Dekker split of fp32)
__device__ __half g_Hh[67108864];   // hidden hi  [l][t][d]   (= RN16(hidden))
__device__ __half g_Hl[67108864];   // hidden lo
__device__ __half g_Wh[67108864];   // W_s1 hi, TRANSPOSED [l][e][d]
__device__ __half g_Wl[67108864];   // W_s1 lo, TRANSPOSED [l][e][d]
__device__ __half g_R1h[4194304];   // W_r1 hi, TRANSPOSED [l][r][d]
__device__ __half g_R1l[4194304];   // W_r1 lo

// ===========================================================================
// Helpers (sm_80-compatible PTX only)
// ===========================================================================
__device__ __forceinline__ uint32_t smem_u32(const void* p) {
    uint32_t a;
    asm("{ .reg .u64 t; cvta.to.shared.u64 t, %1; cvt.u32.u64 %0, t; }" : "=r"(a) : "l"(p));
    return a;
}
__device__ __forceinline__ void ldsm_x4(uint32_t* d, uint32_t addr) {
    asm volatile("ldmatrix.sync.aligned.m8n8.x4.shared.b16 {%0,%1,%2,%3}, [%4];"
                 : "=r"(d[0]), "=r"(d[1]), "=r"(d[2]), "=r"(d[3]) : "r"(addr));
}
__device__ __forceinline__ void mma_f16(float* c, const uint32_t* a, uint32_t b0, uint32_t b1) {
    asm volatile(
        "mma.sync.aligned.m16n8k16.row.col.f32.f16.f16.f32 "
        "{%0,%1,%2,%3}, {%4,%5,%6,%7}, {%8,%9}, {%0,%1,%2,%3};"
        : "+f"(c[0]), "+f"(c[1]), "+f"(c[2]), "+f"(c[3])
        : "r"(a[0]), "r"(a[1]), "r"(a[2]), "r"(a[3]), "r"(b0), "r"(b1));
}
// fp16 Dekker split of two fp32 -> packed hi word + lo word
__device__ __forceinline__ void split2(float x, float y, uint32_t& h, uint32_t& l) {
    __half hx = __float2half_rn(x);
    __half hy = __float2half_rn(y);
    __half lx = __float2half_rn(x - __half2float(hx));
    __half ly = __float2half_rn(y - __half2float(hy));
    __half2 th = __halves2half2(hx, hy);
    __half2 tl = __halves2half2(lx, ly);
    h = *reinterpret_cast<uint32_t*>(&th);
    l = *reinterpret_cast<uint32_t*>(&tl);
}
#define CP16(d, s) asm volatile("cp.async.cg.shared.global [%0], [%1], 16;\n" :: "r"(d), "l"(s))
#define CPCOMMIT() asm volatile("cp.async.commit_group;\n" ::: "memory")
#define CPWAIT1()  asm volatile("cp.async.wait_group 1;\n" ::: "memory")
#define CPWAIT2()  asm volatile("cp.async.wait_group 2;\n" ::: "memory")

// ---------------------------------------------------------------------------
// Pre-split kernels
// ---------------------------------------------------------------------------
__global__ __launch_bounds__(256) void split_h_kernel(const float* __restrict__ h)
{
    size_t idx = ((size_t)blockIdx.x * 256 + threadIdx.x) * 4;
    float4 v = *(const float4*)(h + idx);
    uint32_t h0, l0, h1, l1;
    split2(v.x, v.y, h0, l0);
    split2(v.z, v.w, h1, l1);
    *(uint2*)&g_Hh[idx] = make_uint2(h0, h1);
    *(uint2*)&g_Hl[idx] = make_uint2(l0, l1);
}

// W_s1 [l][d][e] -> g_W{h,l} transposed [l][e][d]
__global__ __launch_bounds__(256) void split_w_kernel(const float* __restrict__ W)
{
    __shared__ float s[64][129];
    const int l = blockIdx.z, kb = blockIdx.y, eb = blockIdx.x;
    const int tid = threadIdx.x;
    const float* src = W + ((size_t)l * ND + kb * 64) * ND + eb * 128;
    #pragma unroll
    for (int i = 0; i < 8; i++) {
        int idx = tid + i * 256;
        int k = idx >> 5;
        int e4 = (idx & 31) * 4;
        float4 v = *(const float4*)(src + (size_t)k * ND + e4);
        s[k][e4] = v.x; s[k][e4 + 1] = v.y; s[k][e4 + 2] = v.z; s[k][e4 + 3] = v.w;
    }
    __syncthreads();
    const int e  = tid >> 1;
    const int kh = (tid & 1) * 32;
    uint32_t hw[16], lw[16];
    #pragma unroll
    for (int j = 0; j < 16; j++)
        split2(s[kh + 2 * j][e], s[kh + 2 * j + 1][e], hw[j], lw[j]);
    size_t doff = ((size_t)l * ND + eb * 128 + e) * ND + kb * 64 + kh;
    #pragma unroll
    for (int q = 0; q < 4; q++) {
        *(uint4*)&g_Wh[doff + q * 8] = make_uint4(hw[4*q], hw[4*q+1], hw[4*q+2], hw[4*q+3]);
        *(uint4*)&g_Wl[doff + q * 8] = make_uint4(lw[4*q], lw[4*q+1], lw[4*q+2], lw[4*q+3]);
    }
}

// W_r1 [l][d][r] -> g_R1{h,l} transposed [l][r][d]
__global__ __launch_bounds__(256) void split_r1_kernel(const float* __restrict__ W)
{
    __shared__ float s[64][129];
    const int l = blockIdx.y, kb = blockIdx.x;
    const int tid = threadIdx.x;
    const float* src = W + ((size_t)l * ND + kb * 64) * NR;
    #pragma unroll
    for (int i = 0; i < 8; i++) {
        int idx = tid + i * 256;
        int k  = idx >> 5;
        int r4 = (idx & 31) * 4;
        float4 v = *(const float4*)(src + (size_t)k * NR + r4);
        s[k][r4] = v.x; s[k][r4 + 1] = v.y; s[k][r4 + 2] = v.z; s[k][r4 + 3] = v.w;
    }
    __syncthreads();
    const int r  = tid >> 1;
    const int kh = (tid & 1) * 32;
    uint32_t hw[16], lw[16];
    #pragma unroll
    for (int j = 0; j < 16; j++)
        split2(s[kh + 2 * j][r], s[kh + 2 * j + 1][r], hw[j], lw[j]);
    size_t doff = ((size_t)l * NR + r) * ND + kb * 64 + kh;
    #pragma unroll
    for (int q = 0; q < 4; q++) {
        *(uint4*)&g_R1h[doff + q * 8] = make_uint4(hw[4*q], hw[4*q+1], hw[4*q+2], hw[4*q+3]);
        *(uint4*)&g_R1l[doff + q * 8] = make_uint4(lw[4*q], lw[4*q+1], lw[4*q+2], lw[4*q+3]);
    }
}

// ===========================================================================
// Common tile constants
// ===========================================================================
#define KC       32
#define ASTRIDE  40

// ---------------------------------------------------------------------------
// Router GEMM on tensor cores (fp16 hi/lo x3 products): approx probs.
// (proven R9 version, unchanged)
// ---------------------------------------------------------------------------
#define R_OFF_AL 10240
#define R_OFF_BH 20480
#define R_OFF_BL 30720
#define R_BUFB   40960
#define RT_MISC  163840
#define RT_SM    167424

__global__ __launch_bounds__(256, 1) void router_mm(
    const float* __restrict__ b_r1,
    const float* __restrict__ W_r2,
    const float* __restrict__ b_r2)
{
    extern __shared__ char sm[];
    const int l   = blockIdx.y;
    const int t0  = blockIdx.x * 128;
    const int tid = threadIdx.x;
    const int w   = tid >> 5;
    const int lane = tid & 31;
    const uint32_t sbase = smem_u32(sm);

    float* sB1   = (float*)(sm + RT_MISC);
    float* sW2   = (float*)(sm + RT_MISC + 512);
    float* spart = (float*)(sm + RT_MISC + 1024);
    if (tid < NR) {
        sB1[tid] = b_r1[l * NR + tid];
        sW2[tid] = W_r2[l * NR + tid];
    }
    __syncthreads();

    const int row = tid >> 1;
    const int kh  = (tid & 1) * 16;
    const __half* aH = g_Hh + ((size_t)l * NT + t0 + row) * ND + kh;
    const __half* aL = g_Hl + ((size_t)l * NT + t0 + row) * ND + kh;
    const __half* bH = g_R1h + ((size_t)l * NR + row) * ND + kh;
    const __half* bL = g_R1l + ((size_t)l * NR + row) * ND + kh;
    const uint32_t stsA = (uint32_t)(row * ASTRIDE + kh) * 2;

    const int wm = w & 1, wn = w >> 1;
    const int m_base = wm * 64, n_base = wn * 32;
    const int frow = lane & 15;
    const int fcol = (lane >> 4) * 8;

    float acc[4][4][4];
    #pragma unroll
    for (int i = 0; i < 4; i++)
        #pragma unroll
        for (int g = 0; g < 4; g++)
            #pragma unroll
            for (int e = 0; e < 4; e++) acc[i][g][e] = 0.f;

    #define R_ISSUE(cc, buf) do {                                               \
        uint32_t bb = sbase + (buf) * R_BUFB;                                   \
        const __half* pah = aH + (cc) * KC;                                     \
        const __half* pal = aL + (cc) * KC;                                     \
        const __half* pbh = bH + (cc) * KC;                                     \
        const __half* pbl = bL + (cc) * KC;                                     \
        CP16(bb + stsA,            pah); CP16(bb + stsA + 16,            pah + 8); \
        CP16(bb + R_OFF_AL + stsA, pal); CP16(bb + R_OFF_AL + stsA + 16, pal + 8); \
        CP16(bb + R_OFF_BH + stsA, pbh); CP16(bb + R_OFF_BH + stsA + 16, pbh + 8); \
        CP16(bb + R_OFF_BL + stsA, pbl); CP16(bb + R_OFF_BL + stsA + 16, pbl + 8); \
        CPCOMMIT();                                                             \
    } while (0)

    #define R_COMPUTE(buf) do {                                                 \
        const uint32_t bb = sbase + (buf) * R_BUFB;                             \
        _Pragma("unroll")                                                       \
        for (int s = 0; s < 2; s++) {                                           \
            const int k0 = s * 16;                                              \
            uint32_t ah[4][4], al[4][4], bh[2][4], bl[2][4];                    \
            const uint32_t a_ad = bb + ((m_base + frow) * ASTRIDE + k0 + fcol) * 2; \
            _Pragma("unroll")                                                   \
            for (int i = 0; i < 4; i++) {                                       \
                ldsm_x4(ah[i], a_ad + i * (16 * ASTRIDE * 2));                  \
                ldsm_x4(al[i], a_ad + R_OFF_AL + i * (16 * ASTRIDE * 2));       \
            }                                                                   \
            const uint32_t b_ad = bb + R_OFF_BH + ((n_base + frow) * ASTRIDE + k0 + fcol) * 2; \
            _Pragma("unroll")                                                   \
            for (int j = 0; j < 2; j++) {                                       \
                ldsm_x4(bh[j], b_ad + j * (16 * ASTRIDE * 2));                  \
                ldsm_x4(bl[j], b_ad + (R_OFF_BL - R_OFF_BH) + j * (16 * ASTRIDE * 2)); \
            }                                                                   \
            _Pragma("unroll")                                                   \
            for (int i = 0; i < 4; i++) {                                       \
                _Pragma("unroll")                                               \
                for (int jj = 0; jj < 2; jj++) {                                \
                    _Pragma("unroll")                                           \
                    for (int hi = 0; hi < 2; hi++) {                            \
                        const int g = jj * 2 + hi;                              \
                        mma_f16(acc[i][g], ah[i], bh[jj][hi], bh[jj][hi + 2]);  \
                        mma_f16(acc[i][g], ah[i], bl[jj][hi], bl[jj][hi + 2]);  \
                        mma_f16(acc[i][g], al[i], bh[jj][hi], bh[jj][hi + 2]);  \
                    }                                                           \
                }                                                               \
            }                                                                   \
        }                                                                       \
    } while (0)

    R_ISSUE(0, 0); R_ISSUE(1, 1); R_ISSUE(2, 2);
    for (int c = 0; c < ND / KC; c++) {
        CPWAIT2();
        __syncthreads();
        R_COMPUTE(c & 3);
        if (c + 3 < ND / KC) R_ISSUE(c + 3, (c + 3) & 3);
    }

    // epilogue: relu(acc + b1) . w2, reduce to per-token partial
    const int tq = lane >> 2;
    const int tr = lane & 3;
    #pragma unroll
    for (int i = 0; i < 4; i++) {
        float sa = 0.f, sb = 0.f;
        #pragma unroll
        for (int g = 0; g < 4; g++) {
            const int c0 = n_base + g * 8 + tr * 2;
            const float b0 = sB1[c0], b1v = sB1[c0 + 1];
            const float w0 = sW2[c0], w1v = sW2[c0 + 1];
            sa += fmaxf(acc[i][g][0] + b0, 0.f) * w0 + fmaxf(acc[i][g][1] + b1v, 0.f) * w1v;
            sb += fmaxf(acc[i][g][2] + b0, 0.f) * w0 + fmaxf(acc[i][g][3] + b1v, 0.f) * w1v;
        }
        sa += __shfl_down_sync(0xffffffffu, sa, 2, 4);
        sa += __shfl_down_sync(0xffffffffu, sa, 1, 4);
        sb += __shfl_down_sync(0xffffffffu, sb, 2, 4);
        sb += __shfl_down_sync(0xffffffffu, sb, 1, 4);
        if (tr == 0) {
            spart[wn * 128 + m_base + i * 16 + tq]     = sa;
            spart[wn * 128 + m_base + i * 16 + tq + 8] = sb;
        }
    }
    __syncthreads();

    if (tid < 128) {
        float logit = spart[tid] + spart[128 + tid] + spart[256 + tid] + spart[384 + tid]
                    + b_r2[l];
        g_probs[l * NT + t0 + tid] = 1.0f / (1.0f + expf(-logit));
    }
}

// ---------------------------------------------------------------------------
// Top-K via exhaustive rank — 8 blocks/layer, 1 token/thread
// ---------------------------------------------------------------------------
__global__ __launch_bounds__(256) void topk_kernel()
{
    __shared__ float sp[NT];
    const int l   = blockIdx.x >> 3;
    const int seg = blockIdx.x & 7;
    for (int i = threadIdx.x; i < NT; i += 256) sp[i] = g_probs[l * NT + i];
    __syncthreads();

    const int t = seg * 256 + threadIdx.x;
    const float p = sp[t];
    int rank = 0;
    #pragma unroll 8
    for (int j = 0; j < NT; j++) {
        float q = sp[j];
        rank += (q > p) || (q == p && j < t);
    }
    g_order[l * NT + rank] = t;
}

// ---------------------------------------------------------------------------
// Find tokens within BAND_DELTA of the K-th prob
// ---------------------------------------------------------------------------
__global__ __launch_bounds__(256) void band_find_kernel()
{
    __shared__ int cnt;
    __shared__ float vK;
    const int l = blockIdx.x;
    if (threadIdx.x == 0) {
        cnt = 0;
        vK = g_probs[l * NT + g_order[l * NT + NK - 1]];
    }
    __syncthreads();
    for (int t = threadIdx.x; t < NT; t += 256) {
        float p = g_probs[l * NT + t];
        if (fabsf(p - vK) <= BAND_DELTA) {
            int i = atomicAdd(&cnt, 1);
            if (i < BANDCAP) g_band[l * BANDCAP + i] = t;
        }
    }
    __syncthreads();
    if (threadIdx.x == 0) g_bandcnt[l] = cnt < BANDCAP ? cnt : BANDCAP;
}

// ---------------------------------------------------------------------------
// Exact fp32 recompute of band tokens' probs
// ---------------------------------------------------------------------------
__global__ __launch_bounds__(128) void exact_fix_kernel(
    const float* __restrict__ hidden,
    const float* __restrict__ W_r1,
    const float* __restrict__ b_r1,
    const float* __restrict__ W_r2,
    const float* __restrict__ b_r2)
{
    const int i = blockIdx.x, l = blockIdx.y;
    if (i >= g_bandcnt[l]) return;
    const int t = g_band[l * BANDCAP + i];
    const int r = threadIdx.x;

    const float* h = hidden + ((size_t)l * NT + t) * ND;
    const float* w = W_r1 + (size_t)l * ND * NR + r;
    float acc = 0.f;
    #pragma unroll 8
    for (int d = 0; d < ND; d++) acc += h[d] * w[(size_t)d * NR];

    float v = fmaxf(acc + b_r1[l * NR + r], 0.f) * W_r2[l * NR + r];

    __shared__ float red[128];
    red[r] = v;
    __syncthreads();
    #pragma unroll
    for (int s = 64; s > 0; s >>= 1) {
        if (r < s) red[r] += red[r + s];
        __syncthreads();
    }
    if (r == 0) {
        float logit = red[0] + b_r2[l];
        g_probs[l * NT + t] = 1.0f / (1.0f + expf(-logit));
    }
}

// ---------------------------------------------------------------------------
// Copy s2 rows (proven)
// ---------------------------------------------------------------------------
__global__ __launch_bounds__(128) void copy_kernel(
    const float* __restrict__ s2, float* __restrict__ out)
{
    const int l = blockIdx.x >> 10;
    const int i = blockIdx.x & (NK - 1);
    const int t = g_order[l * NT + i];
    const float4* src = (const float4*)(s2 + ((size_t)l * NT + t) * ND);
    float4*       dst = (float4*)(out + ((size_t)l * NT + t) * ND);
    #pragma unroll
    for (int j = threadIdx.x; j < ND / 4; j += 128) dst[j] = src[j];
}

// ---------------------------------------------------------------------------
// s1 GEMM: fp16 HMMA, 2 products (Ah*Bh + Ah*Bl) — proven 1.47e-4 accuracy.
// CTA 128(M, gathered) x 128(N), K-chunk 32, 3-stage cp.async pipeline.
// Per buffer: Ah / Bh / Bl, 10240 B each = 30720 B; 3 buffers = 92160 B
// -> 92.7 KB smem/CTA => 2 CTAs/SM (occupancy experiment, minBlocks=2).
// ---------------------------------------------------------------------------
#define S_OFF_BH 10240
#define S_OFF_BL 20480
#define S_BUFB   30720
#define S_ROWS   92160
#define S_SM     92672

__global__ __launch_bounds__(256, 2) void s1_gemm_cp(
    const float* __restrict__ b_s1,
    float* __restrict__ out)
{
    extern __shared__ char sm[];
    const int l   = blockIdx.z;
    const int n0  = blockIdx.x * 128;
    const int r0  = blockIdx.y * 128;
    const int tid = threadIdx.x;
    const int w   = tid >> 5;
    const int lane = tid & 31;
    const uint32_t sbase = smem_u32(sm);

    int* srows = (int*)(sm + S_ROWS);
    if (tid < 128) srows[tid] = g_order[l * NT + NK + r0 + tid];
    __syncthreads();

    const int row = tid >> 1;
    const int kh  = (tid & 1) * 16;
    const __half* aH = g_Hh + ((size_t)l * NT + srows[row]) * ND + kh;
    const __half* bH = g_Wh + ((size_t)l * ND + n0 + row) * ND + kh;
    const __half* bL = g_Wl + ((size_t)l * ND + n0 + row) * ND + kh;
    const uint32_t stsA = (uint32_t)(row * ASTRIDE + kh) * 2;

    const int wm = w & 1, wn = w >> 1;
    const int m_base = wm * 64, n_base = wn * 32;
    const int frow = lane & 15;
    const int fcol = (lane >> 4) * 8;

    float acc[4][4][4];
    #pragma unroll
    for (int i = 0; i < 4; i++)
        #pragma unroll
        for (int g = 0; g < 4; g++)
            #pragma unroll
            for (int e = 0; e < 4; e++) acc[i][g][e] = 0.f;

    #define S_ISSUE(cc, buf) do {                                               \
        uint32_t bb = sbase + (buf) * S_BUFB;                                   \
        const __half* pah = aH + (cc) * KC;                                     \
        const __half* pbh = bH + (cc) * KC;                                     \
        const __half* pbl = bL + (cc) * KC;                                     \
        CP16(bb + stsA,            pah); CP16(bb + stsA + 16,            pah + 8); \
        CP16(bb + S_OFF_BH + stsA, pbh); CP16(bb + S_OFF_BH + stsA + 16, pbh + 8); \
        CP16(bb + S_OFF_BL + stsA, pbl); CP16(bb + S_OFF_BL + stsA + 16, pbl + 8); \
        CPCOMMIT();                                                             \
    } while (0)

    #define S_COMPUTE(buf) do {                                                 \
        const uint32_t bb = sbase + (buf) * S_BUFB;                             \
        _Pragma("unroll")                                                       \
        for (int s = 0; s < 2; s++) {                                           \
            const int k0 = s * 16;                                              \
            uint32_t ah[4][4], bh[2][4], bl[2][4];                              \
            const uint32_t a_ad = bb + ((m_base + frow) * ASTRIDE + k0 + fcol) * 2; \
            _Pragma("unroll")                                                   \
            for (int i = 0; i < 4; i++)                                         \
                ldsm_x4(ah[i], a_ad + i * (16 * ASTRIDE * 2));                  \
            const uint32_t b_ad = bb + S_OFF_BH + ((n_base + frow) * ASTRIDE + k0 + fcol) * 2; \
            _Pragma("unroll")                                                   \
            for (int j = 0; j < 2; j++) {                                       \
                ldsm_x4(bh[j], b_ad + j * (16 * ASTRIDE * 2));                  \
                ldsm_x4(bl[j], b_ad + (S_OFF_BL - S_OFF_BH) + j * (16 * ASTRIDE * 2)); \
            }                                                                   \
            _Pragma("unroll")                                                   \
            for (int i = 0; i < 4; i++) {                                       \
                _Pragma("unroll")                                               \
                for (int jj = 0; jj < 2; jj++) {                                \
                    _Pragma("unroll")                                           \
                    for (int hi = 0; hi < 2; hi++) {                            \
                        const int g = jj * 2 + hi;                              \
                        mma_f16(acc[i][g], ah[i], bh[jj][hi], bh[jj][hi + 2]);  \
                        mma_f16(acc[i][g], ah[i], bl[jj][hi], bl[jj][hi + 2]);  \
                    }                                                           \
                }                                                               \
            }                                                                   \
        }                                                                       \
    } while (0)

    S_ISSUE(0, 0); S_ISSUE(1, 1);

    int cb = 0;   // compute buffer (rotates 0,1,2)
    for (int c = 0; c < ND / KC; c++) {
        CPWAIT1();            // group c complete (<=1 younger pending)
        __syncthreads();
        S_COMPUTE(cb);
        if (c + 2 < ND / KC) {
            int ib = cb;      // issue into the buffer just freed... next iter's c+2 slot
            ib = cb + 2; if (ib >= 3) ib -= 3;
            S_ISSUE(c + 2, ib);
        }
        cb = (cb == 2) ? 0 : cb + 1;
        // safety: ISSUE writes buffer (cb_old+2)%3 = (cb_old-1)%3, whose last
        // readers (COMPUTE of chunk c-1) finished before this iter's barrier.
    }

    const int tq = lane >> 2;
    const int tr = lane & 3;
    #pragma unroll
    for (int g = 0; g < 4; g++) {
        const int col = n_base + g * 8 + tr * 2;
        const float bx = __ldg(b_s1 + l * ND + n0 + col);
        const float by = __ldg(b_s1 + l * ND + n0 + col + 1);
        #pragma unroll
        for (int i = 0; i < 4; i++) {
            const int rl = m_base + i * 16 + tq;
            float* o0 = out + ((size_t)l * NT + srows[rl])     * ND + n0 + col;
            float* o1 = out + ((size_t)l * NT + srows[rl + 8]) * ND + n0 + col;
            *(float2*)o0 = make_float2(acc[i][g][0] + bx, acc[i][g][1] + by);
            *(float2*)o1 = make_float2(acc[i][g][2] + bx, acc[i][g][3] + by);
        }
    }
}

// ---------------------------------------------------------------------------
extern "C" void kernel_launch(void* const* d_in, const int* in_sizes, int n_in,
                              void* d_out, int out_size)
{
    const float* hidden = (const float*)d_in[0];
    const float* s2     = (const float*)d_in[1];
    const float* W_r1   = (const float*)d_in[2];
    const float* b_r1   = (const float*)d_in[3];
    const float* W_r2   = (const float*)d_in[4];
    const float* b_r2   = (const float*)d_in[5];
    const float* W_s1   = (const float*)d_in[6];
    const float* b_s1   = (const float*)d_in[7];
    float* out = (float*)d_out;

    static cudaStream_t sB = nullptr;
    static cudaEvent_t eFork = nullptr, eW = nullptr, eOrd = nullptr, eCopy = nullptr;
    if (!sB) {
        cudaFuncSetAttribute(s1_gemm_cp, cudaFuncAttributeMaxDynamicSharedMemorySize, S_SM);
        cudaFuncSetAttribute(router_mm, cudaFuncAttributeMaxDynamicSharedMemorySize, RT_SM);
        cudaStreamCreateWithFlags(&sB, cudaStreamNonBlocking);
        cudaEventCreateWithFlags(&eFork, cudaEventDisableTiming);
        cudaEventCreateWithFlags(&eW,    cudaEventDisableTiming);
        cudaEventCreateWithFlags(&eOrd,  cudaEventDisableTiming);
        cudaEventCreateWithFlags(&eCopy, cudaEventDisableTiming);
    }

    // fork: side stream does split_w (independent of router chain)
    cudaEventRecord(eFork, 0);
    cudaStreamWaitEvent(sB, eFork, 0);
    split_w_kernel<<<dim3(16, 32, 16), 256, 0, sB>>>(W_s1);
    cudaEventRecord(eW, sB);

    // main chain
    split_h_kernel<<<65536, 256>>>(hidden);
    split_r1_kernel<<<dim3(32, 16), 256>>>(W_r1);
    router_mm<<<dim3(16, 16), 256, RT_SM>>>(b_r1, W_r2, b_r2);
    topk_kernel<<<NL * 8, 256>>>();
    band_find_kernel<<<NL, 256>>>();
    exact_fix_kernel<<<dim3(BANDCAP, NL), 128>>>(hidden, W_r1, b_r1, W_r2, b_r2);
    topk_kernel<<<NL * 8, 256>>>();
    cudaEventRecord(eOrd, 0);

    // side stream: copy overlaps the GEMM (disjoint output rows)
    cudaStreamWaitEvent(sB, eOrd, 0);
    copy_kernel<<<NL * NK, 128, 0, sB>>>(s2, out);
    cudaEventRecord(eCopy, sB);

    // main: GEMM needs split_w done
    cudaStreamWaitEvent(0, eW, 0);
    dim3 g(ND / 128, (NT - NK) / 128, NL);
    s1_gemm_cp<<<g, 256, S_SM>>>(b_s1, out);

    // join
    cudaStreamWaitEvent(0, eCopy, 0);
}

// round 12
// speedup vs baseline: 2.3991x; 1.0867x over previous
#include <cuda_runtime.h>
#include <cuda_fp16.h>
#include <math.h>
#include <stdint.h>

#define NL 16
#define NT 2048
#define ND 2048
#define NR 128
#define NK 1024      // top-k capacity (T * 0.5)
#define BANDCAP 64
#define BAND_DELTA 8e-4f

// Scratch (no device allocation allowed -> __device__ globals)
__device__ float g_probs[NL * NT];
__device__ int   g_order[NL * NT];
__device__ int   g_bandcnt[NL];
__device__ int   g_band[NL * BANDCAP];

// Pre-split fp16 scratch (Dekker split of fp32 where needed)
__device__ __half g_Hh[67108864];   // hidden fp16  [l][t][d]
__device__ __half g_Wh[67108864];   // W_s1 hi, TRANSPOSED [l][e][d]
__device__ __half g_Wl[67108864];   // W_s1 lo, TRANSPOSED [l][e][d]
__device__ __half g_R1h[4194304];   // W_r1 hi, TRANSPOSED [l][r][d]
__device__ __half g_R1l[4194304];   // W_r1 lo

// ===========================================================================
// Helpers (sm_80-compatible PTX only)
// ===========================================================================
__device__ __forceinline__ uint32_t smem_u32(const void* p) {
    uint32_t a;
    asm("{ .reg .u64 t; cvta.to.shared.u64 t, %1; cvt.u32.u64 %0, t; }" : "=r"(a) : "l"(p));
    return a;
}
__device__ __forceinline__ void ldsm_x4(uint32_t* d, uint32_t addr) {
    asm volatile("ldmatrix.sync.aligned.m8n8.x4.shared.b16 {%0,%1,%2,%3}, [%4];"
                 : "=r"(d[0]), "=r"(d[1]), "=r"(d[2]), "=r"(d[3]) : "r"(addr));
}
__device__ __forceinline__ void mma_f16(float* c, const uint32_t* a, uint32_t b0, uint32_t b1) {
    asm volatile(
        "mma.sync.aligned.m16n8k16.row.col.f32.f16.f16.f32 "
        "{%0,%1,%2,%3}, {%4,%5,%6,%7}, {%8,%9}, {%0,%1,%2,%3};"
        : "+f"(c[0]), "+f"(c[1]), "+f"(c[2]), "+f"(c[3])
        : "r"(a[0]), "r"(a[1]), "r"(a[2]), "r"(a[3]), "r"(b0), "r"(b1));
}
// fp16 Dekker split of two fp32 -> packed hi word + lo word
__device__ __forceinline__ void split2(float x, float y, uint32_t& h, uint32_t& l) {
    __half hx = __float2half_rn(x);
    __half hy = __float2half_rn(y);
    __half lx = __float2half_rn(x - __half2float(hx));
    __half ly = __float2half_rn(y - __half2float(hy));
    __half2 th = __halves2half2(hx, hy);
    __half2 tl = __halves2half2(lx, ly);
    h = *reinterpret_cast<uint32_t*>(&th);
    l = *reinterpret_cast<uint32_t*>(&tl);
}
__device__ __forceinline__ uint32_t pack_hi2(float x, float y) {
    __half2 t = __halves2half2(__float2half_rn(x), __float2half_rn(y));
    return *reinterpret_cast<uint32_t*>(&t);
}
#define CP16(d, s) asm volatile("cp.async.cg.shared.global [%0], [%1], 16;\n" :: "r"(d), "l"(s))
#define CPCOMMIT() asm volatile("cp.async.commit_group;\n" ::: "memory")
#define CPWAIT1()  asm volatile("cp.async.wait_group 1;\n" ::: "memory")

// ---------------------------------------------------------------------------
// Pre-split kernels
// ---------------------------------------------------------------------------
__global__ __launch_bounds__(256) void split_h_kernel(const float* __restrict__ h)
{
    size_t idx = ((size_t)blockIdx.x * 256 + threadIdx.x) * 4;
    float4 v = *(const float4*)(h + idx);
    uint32_t h0 = pack_hi2(v.x, v.y);
    uint32_t h1 = pack_hi2(v.z, v.w);
    *(uint2*)&g_Hh[idx] = make_uint2(h0, h1);
}

// W_s1 [l][d][e] -> g_W{h,l} transposed [l][e][d]
__global__ __launch_bounds__(256) void split_w_kernel(const float* __restrict__ W)
{
    __shared__ float s[64][129];
    const int l = blockIdx.z, kb = blockIdx.y, eb = blockIdx.x;
    const int tid = threadIdx.x;
    const float* src = W + ((size_t)l * ND + kb * 64) * ND + eb * 128;
    #pragma unroll
    for (int i = 0; i < 8; i++) {
        int idx = tid + i * 256;
        int k = idx >> 5;
        int e4 = (idx & 31) * 4;
        float4 v = *(const float4*)(src + (size_t)k * ND + e4);
        s[k][e4] = v.x; s[k][e4 + 1] = v.y; s[k][e4 + 2] = v.z; s[k][e4 + 3] = v.w;
    }
    __syncthreads();
    const int e  = tid >> 1;
    const int kh = (tid & 1) * 32;
    uint32_t hw[16], lw[16];
    #pragma unroll
    for (int j = 0; j < 16; j++)
        split2(s[kh + 2 * j][e], s[kh + 2 * j + 1][e], hw[j], lw[j]);
    size_t doff = ((size_t)l * ND + eb * 128 + e) * ND + kb * 64 + kh;
    #pragma unroll
    for (int q = 0; q < 4; q++) {
        *(uint4*)&g_Wh[doff + q * 8] = make_uint4(hw[4*q], hw[4*q+1], hw[4*q+2], hw[4*q+3]);
        *(uint4*)&g_Wl[doff + q * 8] = make_uint4(lw[4*q], lw[4*q+1], lw[4*q+2], lw[4*q+3]);
    }
}

// W_r1 [l][d][r] -> g_R1{h,l} transposed [l][r][d]
__global__ __launch_bounds__(256) void split_r1_kernel(const float* __restrict__ W)
{
    __shared__ float s[64][129];
    const int l = blockIdx.y, kb = blockIdx.x;
    const int tid = threadIdx.x;
    const float* src = W + ((size_t)l * ND + kb * 64) * NR;
    #pragma unroll
    for (int i = 0; i < 8; i++) {
        int idx = tid + i * 256;
        int k  = idx >> 5;
        int r4 = (idx & 31) * 4;
        float4 v = *(const float4*)(src + (size_t)k * NR + r4);
        s[k][r4] = v.x; s[k][r4 + 1] = v.y; s[k][r4 + 2] = v.z; s[k][r4 + 3] = v.w;
    }
    __syncthreads();
    const int r  = tid >> 1;
    const int kh = (tid & 1) * 32;
    uint32_t hw[16], lw[16];
    #pragma unroll
    for (int j = 0; j < 16; j++)
        split2(s[kh + 2 * j][r], s[kh + 2 * j + 1][r], hw[j], lw[j]);
    size_t doff = ((size_t)l * NR + r) * ND + kb * 64 + kh;
    #pragma unroll
    for (int q = 0; q < 4; q++) {
        *(uint4*)&g_R1h[doff + q * 8] = make_uint4(hw[4*q], hw[4*q+1], hw[4*q+2], hw[4*q+3]);
        *(uint4*)&g_R1l[doff + q * 8] = make_uint4(lw[4*q], lw[4*q+1], lw[4*q+2], lw[4*q+3]);
    }
}

// ===========================================================================
// Common tile constants + shared 2-product GEMM core (proven R11 structure):
// A fp16 single-rounded; B split hi/lo. 3 smem arrays, 3-stage pipeline,
// 2 CTAs/SM. Caller provides aH/bH/bL pointers and epilogue.
// ===========================================================================
#define KC       32
#define ASTRIDE  40
#define C_OFF_BH 10240
#define C_OFF_BL 20480
#define C_BUFB   30720
#define C_MISC   92160

#define CORE_ISSUE(cc, buf) do {                                                \
    uint32_t bb = sbase + (buf) * C_BUFB;                                       \
    const __half* pah = aH + (cc) * KC;                                         \
    const __half* pbh = bH + (cc) * KC;                                         \
    const __half* pbl = bL + (cc) * KC;                                         \
    CP16(bb + stsA,            pah); CP16(bb + stsA + 16,            pah + 8);  \
    CP16(bb + C_OFF_BH + stsA, pbh); CP16(bb + C_OFF_BH + stsA + 16, pbh + 8);  \
    CP16(bb + C_OFF_BL + stsA, pbl); CP16(bb + C_OFF_BL + stsA + 16, pbl + 8);  \
    CPCOMMIT();                                                                 \
} while (0)

#define CORE_COMPUTE(buf) do {                                                  \
    const uint32_t bb = sbase + (buf) * C_BUFB;                                 \
    _Pragma("unroll")                                                           \
    for (int s = 0; s < 2; s++) {                                               \
        const int k0 = s * 16;                                                  \
        uint32_t ah[4][4], bh[2][4], bl[2][4];                                  \
        const uint32_t a_ad = bb + ((m_base + frow) * ASTRIDE + k0 + fcol) * 2; \
        _Pragma("unroll")                                                       \
        for (int i = 0; i < 4; i++)                                             \
            ldsm_x4(ah[i], a_ad + i * (16 * ASTRIDE * 2));                      \
        const uint32_t b_ad = bb + C_OFF_BH + ((n_base + frow) * ASTRIDE + k0 + fcol) * 2; \
        _Pragma("unroll")                                                       \
        for (int j = 0; j < 2; j++) {                                           \
            ldsm_x4(bh[j], b_ad + j * (16 * ASTRIDE * 2));                      \
            ldsm_x4(bl[j], b_ad + (C_OFF_BL - C_OFF_BH) + j * (16 * ASTRIDE * 2)); \
        }                                                                       \
        _Pragma("unroll")                                                       \
        for (int i = 0; i < 4; i++) {                                           \
            _Pragma("unroll")                                                   \
            for (int jj = 0; jj < 2; jj++) {                                    \
                _Pragma("unroll")                                               \
                for (int hi = 0; hi < 2; hi++) {                                \
                    const int g = jj * 2 + hi;                                  \
                    mma_f16(acc[i][g], ah[i], bh[jj][hi], bh[jj][hi + 2]);      \
                    mma_f16(acc[i][g], ah[i], bl[jj][hi], bl[jj][hi + 2]);      \
                }                                                               \
            }                                                                   \
        }                                                                       \
    }                                                                           \
} while (0)

#define CORE_MAINLOOP()                                                         \
    CORE_ISSUE(0, 0); CORE_ISSUE(1, 1);                                         \
    {                                                                           \
        int cb = 0;                                                             \
        for (int c = 0; c < ND / KC; c++) {                                     \
            CPWAIT1();                                                          \
            __syncthreads();                                                    \
            CORE_COMPUTE(cb);                                                   \
            if (c + 2 < ND / KC) {                                              \
                int ib = cb + 2; if (ib >= 3) ib -= 3;                          \
                CORE_ISSUE(c + 2, ib);                                          \
            }                                                                   \
            cb = (cb == 2) ? 0 : cb + 1;                                        \
        }                                                                       \
    }

// ---------------------------------------------------------------------------
// Router GEMM (fp16 2-product, band-repaired): approx probs.
// CTA: 128 tokens x 128 R. Same core as s1 GEMM -> 2 CTAs/SM.
// ---------------------------------------------------------------------------
#define RT_SM    95744    // C_MISC + sB1 512 + sW2 512 + spart 2048 + pad

__global__ __launch_bounds__(256, 2) void router_mm(
    const float* __restrict__ b_r1,
    const float* __restrict__ W_r2,
    const float* __restrict__ b_r2)
{
    extern __shared__ char sm[];
    const int l   = blockIdx.y;
    const int t0  = blockIdx.x * 128;
    const int tid = threadIdx.x;
    const int w   = tid >> 5;
    const int lane = tid & 31;
    const uint32_t sbase = smem_u32(sm);

    float* sB1   = (float*)(sm + C_MISC);
    float* sW2   = (float*)(sm + C_MISC + 512);
    float* spart = (float*)(sm + C_MISC + 1024);
    if (tid < NR) {
        sB1[tid] = b_r1[l * NR + tid];
        sW2[tid] = W_r2[l * NR + tid];
    }
    __syncthreads();

    const int row = tid >> 1;
    const int kh  = (tid & 1) * 16;
    const __half* aH = g_Hh + ((size_t)l * NT + t0 + row) * ND + kh;
    const __half* bH = g_R1h + ((size_t)l * NR + row) * ND + kh;
    const __half* bL = g_R1l + ((size_t)l * NR + row) * ND + kh;
    const uint32_t stsA = (uint32_t)(row * ASTRIDE + kh) * 2;

    const int wm = w & 1, wn = w >> 1;
    const int m_base = wm * 64, n_base = wn * 32;
    const int frow = lane & 15;
    const int fcol = (lane >> 4) * 8;

    float acc[4][4][4];
    #pragma unroll
    for (int i = 0; i < 4; i++)
        #pragma unroll
        for (int g = 0; g < 4; g++)
            #pragma unroll
            for (int e = 0; e < 4; e++) acc[i][g][e] = 0.f;

    CORE_MAINLOOP()

    // epilogue: relu(acc + b1) . w2, reduce to per-token partial
    const int tq = lane >> 2;
    const int tr = lane & 3;
    #pragma unroll
    for (int i = 0; i < 4; i++) {
        float sa = 0.f, sb = 0.f;
        #pragma unroll
        for (int g = 0; g < 4; g++) {
            const int c0 = n_base + g * 8 + tr * 2;
            const float b0 = sB1[c0], b1v = sB1[c0 + 1];
            const float w0 = sW2[c0], w1v = sW2[c0 + 1];
            sa += fmaxf(acc[i][g][0] + b0, 0.f) * w0 + fmaxf(acc[i][g][1] + b1v, 0.f) * w1v;
            sb += fmaxf(acc[i][g][2] + b0, 0.f) * w0 + fmaxf(acc[i][g][3] + b1v, 0.f) * w1v;
        }
        sa += __shfl_down_sync(0xffffffffu, sa, 2, 4);
        sa += __shfl_down_sync(0xffffffffu, sa, 1, 4);
        sb += __shfl_down_sync(0xffffffffu, sb, 2, 4);
        sb += __shfl_down_sync(0xffffffffu, sb, 1, 4);
        if (tr == 0) {
            spart[wn * 128 + m_base + i * 16 + tq]     = sa;
            spart[wn * 128 + m_base + i * 16 + tq + 8] = sb;
        }
    }
    __syncthreads();

    if (tid < 128) {
        float logit = spart[tid] + spart[128 + tid] + spart[256 + tid] + spart[384 + tid]
                    + b_r2[l];
        g_probs[l * NT + t0 + tid] = 1.0f / (1.0f + expf(-logit));
    }
}

// ---------------------------------------------------------------------------
// Top-K via exhaustive rank — 8 blocks/layer, 1 token/thread
// ---------------------------------------------------------------------------
__global__ __launch_bounds__(256) void topk_kernel()
{
    __shared__ float sp[NT];
    const int l   = blockIdx.x >> 3;
    const int seg = blockIdx.x & 7;
    for (int i = threadIdx.x; i < NT; i += 256) sp[i] = g_probs[l * NT + i];
    __syncthreads();

    const int t = seg * 256 + threadIdx.x;
    const float p = sp[t];
    int rank = 0;
    #pragma unroll 8
    for (int j = 0; j < NT; j++) {
        float q = sp[j];
        rank += (q > p) || (q == p && j < t);
    }
    g_order[l * NT + rank] = t;
}

// ---------------------------------------------------------------------------
// Find tokens within BAND_DELTA of the K-th prob
// ---------------------------------------------------------------------------
__global__ __launch_bounds__(256) void band_find_kernel()
{
    __shared__ int cnt;
    __shared__ float vK;
    const int l = blockIdx.x;
    if (threadIdx.x == 0) {
        cnt = 0;
        vK = g_probs[l * NT + g_order[l * NT + NK - 1]];
    }
    __syncthreads();
    for (int t = threadIdx.x; t < NT; t += 256) {
        float p = g_probs[l * NT + t];
        if (fabsf(p - vK) <= BAND_DELTA) {
            int i = atomicAdd(&cnt, 1);
            if (i < BANDCAP) g_band[l * BANDCAP + i] = t;
        }
    }
    __syncthreads();
    if (threadIdx.x == 0) g_bandcnt[l] = cnt < BANDCAP ? cnt : BANDCAP;
}

// ---------------------------------------------------------------------------
// Exact fp32 recompute of band tokens' probs
// ---------------------------------------------------------------------------
__global__ __launch_bounds__(128) void exact_fix_kernel(
    const float* __restrict__ hidden,
    const float* __restrict__ W_r1,
    const float* __restrict__ b_r1,
    const float* __restrict__ W_r2,
    const float* __restrict__ b_r2)
{
    const int i = blockIdx.x, l = blockIdx.y;
    if (i >= g_bandcnt[l]) return;
    const int t = g_band[l * BANDCAP + i];
    const int r = threadIdx.x;

    const float* h = hidden + ((size_t)l * NT + t) * ND;
    const float* w = W_r1 + (size_t)l * ND * NR + r;
    float acc = 0.f;
    #pragma unroll 8
    for (int d = 0; d < ND; d++) acc += h[d] * w[(size_t)d * NR];

    float v = fmaxf(acc + b_r1[l * NR + r], 0.f) * W_r2[l * NR + r];

    __shared__ float red[128];
    red[r] = v;
    __syncthreads();
    #pragma unroll
    for (int s = 64; s > 0; s >>= 1) {
        if (r < s) red[r] += red[r + s];
        __syncthreads();
    }
    if (r == 0) {
        float logit = red[0] + b_r2[l];
        g_probs[l * NT + t] = 1.0f / (1.0f + expf(-logit));
    }
}

// ---------------------------------------------------------------------------
// Copy s2 rows (proven)
// ---------------------------------------------------------------------------
__global__ __launch_bounds__(128) void copy_kernel(
    const float* __restrict__ s2, float* __restrict__ out)
{
    const int l = blockIdx.x >> 10;
    const int i = blockIdx.x & (NK - 1);
    const int t = g_order[l * NT + i];
    const float4* src = (const float4*)(s2 + ((size_t)l * NT + t) * ND);
    float4*       dst = (float4*)(out + ((size_t)l * NT + t) * ND);
    #pragma unroll
    for (int j = threadIdx.x; j < ND / 4; j += 128) dst[j] = src[j];
}

// ---------------------------------------------------------------------------
// s1 GEMM: fp16 HMMA, 2 products (Ah*Bh + Ah*Bl) — proven R11 version.
// ---------------------------------------------------------------------------
#define S_SM     92672    // C_MISC + rows 512

__global__ __launch_bounds__(256, 2) void s1_gemm_cp(
    const float* __restrict__ b_s1,
    float* __restrict__ out)
{
    extern __shared__ char sm[];
    const int l   = blockIdx.z;
    const int n0  = blockIdx.x * 128;
    const int r0  = blockIdx.y * 128;
    const int tid = threadIdx.x;
    const int w   = tid >> 5;
    const int lane = tid & 31;
    const uint32_t sbase = smem_u32(sm);

    int* srows = (int*)(sm + C_MISC);
    if (tid < 128) srows[tid] = g_order[l * NT + NK + r0 + tid];
    __syncthreads();

    const int row = tid >> 1;
    const int kh  = (tid & 1) * 16;
    const __half* aH = g_Hh + ((size_t)l * NT + srows[row]) * ND + kh;
    const __half* bH = g_Wh + ((size_t)l * ND + n0 + row) * ND + kh;
    const __half* bL = g_Wl + ((size_t)l * ND + n0 + row) * ND + kh;
    const uint32_t stsA = (uint32_t)(row * ASTRIDE + kh) * 2;

    const int wm = w & 1, wn = w >> 1;
    const int m_base = wm * 64, n_base = wn * 32;
    const int frow = lane & 15;
    const int fcol = (lane >> 4) * 8;

    float acc[4][4][4];
    #pragma unroll
    for (int i = 0; i < 4; i++)
        #pragma unroll
        for (int g = 0; g < 4; g++)
            #pragma unroll
            for (int e = 0; e < 4; e++) acc[i][g][e] = 0.f;

    CORE_MAINLOOP()

    const int tq = lane >> 2;
    const int tr = lane & 3;
    #pragma unroll
    for (int g = 0; g < 4; g++) {
        const int col = n_base + g * 8 + tr * 2;
        const float bx = __ldg(b_s1 + l * ND + n0 + col);
        const float by = __ldg(b_s1 + l * ND + n0 + col + 1);
        #pragma unroll
        for (int i = 0; i < 4; i++) {
            const int rl = m_base + i * 16 + tq;
            float* o0 = out + ((size_t)l * NT + srows[rl])     * ND + n0 + col;
            float* o1 = out + ((size_t)l * NT + srows[rl + 8]) * ND + n0 + col;
            *(float2*)o0 = make_float2(acc[i][g][0] + bx, acc[i][g][1] + by);
            *(float2*)o1 = make_float2(acc[i][g][2] + bx, acc[i][g][3] + by);
        }
    }
}

// ---------------------------------------------------------------------------
extern "C" void kernel_launch(void* const* d_in, const int* in_sizes, int n_in,
                              void* d_out, int out_size)
{
    const float* hidden = (const float*)d_in[0];
    const float* s2     = (const float*)d_in[1];
    const float* W_r1   = (const float*)d_in[2];
    const float* b_r1   = (const float*)d_in[3];
    const float* W_r2   = (const float*)d_in[4];
    const float* b_r2   = (const float*)d_in[5];
    const float* W_s1   = (const float*)d_in[6];
    const float* b_s1   = (const float*)d_in[7];
    float* out = (float*)d_out;

    static cudaStream_t sB = nullptr;
    static cudaEvent_t eFork = nullptr, eR1 = nullptr, eW = nullptr,
                       eOrd = nullptr, eCopy = nullptr;
    if (!sB) {
        cudaFuncSetAttribute(s1_gemm_cp, cudaFuncAttributeMaxDynamicSharedMemorySize, S_SM);
        cudaFuncSetAttribute(router_mm, cudaFuncAttributeMaxDynamicSharedMemorySize, RT_SM);
        cudaStreamCreateWithFlags(&sB, cudaStreamNonBlocking);
        cudaEventCreateWithFlags(&eFork, cudaEventDisableTiming);
        cudaEventCreateWithFlags(&eR1,   cudaEventDisableTiming);
        cudaEventCreateWithFlags(&eW,    cudaEventDisableTiming);
        cudaEventCreateWithFlags(&eOrd,  cudaEventDisableTiming);
        cudaEventCreateWithFlags(&eCopy, cudaEventDisableTiming);
    }

    // fork: side stream does split_r1 (feeds router) then split_w (feeds GEMM)
    cudaEventRecord(eFork, 0);
    cudaStreamWaitEvent(sB, eFork, 0);
    split_r1_kernel<<<dim3(32, 16), 256, 0, sB>>>(W_r1);
    cudaEventRecord(eR1, sB);
    split_w_kernel<<<dim3(16, 32, 16), 256, 0, sB>>>(W_s1);
    cudaEventRecord(eW, sB);

    // main chain
    split_h_kernel<<<65536, 256>>>(hidden);
    cudaStreamWaitEvent(0, eR1, 0);
    router_mm<<<dim3(16, 16), 256, RT_SM>>>(b_r1, W_r2, b_r2);
    topk_kernel<<<NL * 8, 256>>>();
    band_find_kernel<<<NL, 256>>>();
    exact_fix_kernel<<<dim3(BANDCAP, NL), 128>>>(hidden, W_r1, b_r1, W_r2, b_r2);
    topk_kernel<<<NL * 8, 256>>>();
    cudaEventRecord(eOrd, 0);

    // side stream: copy overlaps the GEMM (disjoint output rows)
    cudaStreamWaitEvent(sB, eOrd, 0);
    copy_kernel<<<NL * NK, 128, 0, sB>>>(s2, out);
    cudaEventRecord(eCopy, sB);

    // main: GEMM needs split_w done
    cudaStreamWaitEvent(0, eW, 0);
    dim3 g(ND / 128, (NT - NK) / 128, NL);
    s1_gemm_cp<<<g, 256, S_SM>>>(b_s1, out);

    // join
    cudaStreamWaitEvent(0, eCopy, 0);
}